// round 11
// baseline (speedup 1.0000x reference)
#include <cuda_runtime.h>
#include <cstdint>

// ---------------------------------------------------------------------------
// MultiHeadAttention: out = LN( softmax(QK^T/sqrt(d)) V @ Wo + bo ) + query
// B=4, N=2048, DIM=1024, HEADS=16, DH=64
// Round-10: hi/lo interleaved smem (LDS.64 fragments), fused QKV launch.
// ---------------------------------------------------------------------------

#define BC    4
#define NSEQ  2048
#define DIMC  1024
#define HEADS 16
#define DHEAD 64
#define MTOT  (BC * NSEQ)   // 8192

__device__ float g_q[MTOT * DIMC];     // [B,H,N,DH]  (pre-scaled by 1/8)
__device__ float g_k[MTOT * DIMC];     // [B,H,N,DH]
__device__ float g_v[MTOT * DIMC];     // [B,H,N,DH]
__device__ float g_attn[MTOT * DIMC];  // [B,N,H*DH]
__device__ float g_proj[MTOT * DIMC];  // attn @ Wo + bo

// ---------------------------------------------------------------------------
// bf16 split helpers
// ---------------------------------------------------------------------------
__device__ __forceinline__ uint32_t pack_bf2(float x0, float x1)
{
    uint32_t p;
    asm("cvt.rn.satfinite.bf16x2.f32 %0, %1, %2;" : "=r"(p) : "f"(x1), "f"(x0));
    return p;
}
__device__ __forceinline__ void split_bf2(float x0, float x1,
                                          uint32_t& hi, uint32_t& lo)
{
    uint32_t h = pack_bf2(x0, x1);
    float h0 = __uint_as_float(h << 16);
    float h1 = __uint_as_float(h & 0xffff0000u);
    lo = pack_bf2(x0 - h0, x1 - h1);
    hi = h;
}
__device__ __forceinline__ void mma16(float* d,
                                      uint32_t a0, uint32_t a1, uint32_t a2, uint32_t a3,
                                      uint32_t b0, uint32_t b1)
{
    asm volatile(
        "mma.sync.aligned.m16n8k16.row.col.f32.bf16.bf16.f32 "
        "{%0,%1,%2,%3}, {%4,%5,%6,%7}, {%8,%9}, {%0,%1,%2,%3};\n"
        : "+f"(d[0]), "+f"(d[1]), "+f"(d[2]), "+f"(d[3])
        : "r"(a0), "r"(a1), "r"(a2), "r"(a3), "r"(b0), "r"(b1));
}
// 3-term: D += Ah*Bl + Al*Bh + Ah*Bh
__device__ __forceinline__ void mma3(float* d,
                                     const uint32_t* ah, const uint32_t* al,
                                     uint32_t bh0, uint32_t bh1,
                                     uint32_t bl0, uint32_t bl1)
{
    mma16(d, ah[0], ah[1], ah[2], ah[3], bl0, bl1);
    mma16(d, al[0], al[1], al[2], al[3], bh0, bh1);
    mma16(d, ah[0], ah[1], ah[2], ah[3], bh0, bh1);
}

// ---------------------------------------------------------------------------
// GEMM: 128x128 block, BK=32, 256 threads (8 warps 2x4), warp tile 64x32.
// sA: [128 rows][40 words]  word col = hi/lo interleaved along k (2 per pair)
// sB: [16 kp][264 words]    word 2n = hi, 2n+1 = lo
// ---------------------------------------------------------------------------
#define GAP 40
#define GBP 264

__device__ __forceinline__ void gemm_mainloop(
    const float* __restrict__ A, const float* __restrict__ W,
    int bm, int bn, uint32_t* sA, uint32_t* sB, float acc[4][4][4])
{
    const int tid = threadIdx.x;
    const int lane = tid & 31;
    const int warp = tid >> 5;
    const int gid = lane >> 2;
    const int tg = lane & 3;
    const int wm = warp >> 2;   // 0..1
    const int wn = warp & 3;    // 0..3

    const int bkp = tid >> 4;           // 0..15
    const int bn0 = (tid & 15) * 8;     // 0..120

    float4 pa[4], pb[4];
#pragma unroll
    for (int i = 0; i < 4; i++) {
        int flat = i * 1024 + tid * 4;
        pa[i] = *(const float4*)(A + (bm + (flat >> 5)) * DIMC + (flat & 31));
    }
    pb[0] = *(const float4*)(W + (2 * bkp) * DIMC + bn + bn0);
    pb[1] = *(const float4*)(W + (2 * bkp) * DIMC + bn + bn0 + 4);
    pb[2] = *(const float4*)(W + (2 * bkp + 1) * DIMC + bn + bn0);
    pb[3] = *(const float4*)(W + (2 * bkp + 1) * DIMC + bn + bn0 + 4);

    for (int kb = 0; kb < DIMC / 32; kb++) {
        // ---- store A: uint4 {h0,l0,h1,l1} at row*GAP + col ----
#pragma unroll
        for (int i = 0; i < 4; i++) {
            int flat = i * 1024 + tid * 4;
            int row = flat >> 5, col = flat & 31;
            uint32_t h0, l0, h1, l1;
            split_bf2(pa[i].x, pa[i].y, h0, l0);
            split_bf2(pa[i].z, pa[i].w, h1, l1);
            uint4 u; u.x = h0; u.y = l0; u.z = h1; u.w = l1;
            *(uint4*)&sA[row * GAP + col] = u;
        }
        // ---- store B: pairs across two k rows; words 2n(h), 2n+1(l) ----
        {
            const float* r0 = &pb[0].x;
            const float* r1 = &pb[2].x;
            uint32_t hv[8], lv[8];
#pragma unroll
            for (int j = 0; j < 8; j++)
                split_bf2(r0[j], r1[j], hv[j], lv[j]);
#pragma unroll
            for (int j = 0; j < 4; j++) {
                uint4 u;
                u.x = hv[2 * j]; u.y = lv[2 * j];
                u.z = hv[2 * j + 1]; u.w = lv[2 * j + 1];
                *(uint4*)&sB[bkp * GBP + 2 * bn0 + 4 * j] = u;
            }
        }
        __syncthreads();

        if (kb < DIMC / 32 - 1) {
            int k0 = (kb + 1) * 32;
#pragma unroll
            for (int i = 0; i < 4; i++) {
                int flat = i * 1024 + tid * 4;
                pa[i] = *(const float4*)(A + (bm + (flat >> 5)) * DIMC + k0 + (flat & 31));
            }
            pb[0] = *(const float4*)(W + (k0 + 2 * bkp) * DIMC + bn + bn0);
            pb[1] = *(const float4*)(W + (k0 + 2 * bkp) * DIMC + bn + bn0 + 4);
            pb[2] = *(const float4*)(W + (k0 + 2 * bkp + 1) * DIMC + bn + bn0);
            pb[3] = *(const float4*)(W + (k0 + 2 * bkp + 1) * DIMC + bn + bn0 + 4);
        }

#pragma unroll
        for (int ks = 0; ks < 2; ks++) {
            const int kp0 = ks * 8;
            uint32_t ah[4][4], al[4][4];
#pragma unroll
            for (int mt = 0; mt < 4; mt++) {
                int r = wm * 64 + mt * 16 + gid;
                uint2 a0 = *(uint2*)&sA[r * GAP + 2 * (kp0 + tg)];
                uint2 a1 = *(uint2*)&sA[(r + 8) * GAP + 2 * (kp0 + tg)];
                uint2 a2 = *(uint2*)&sA[r * GAP + 2 * (kp0 + 4 + tg)];
                uint2 a3 = *(uint2*)&sA[(r + 8) * GAP + 2 * (kp0 + 4 + tg)];
                ah[mt][0] = a0.x; al[mt][0] = a0.y;
                ah[mt][1] = a1.x; al[mt][1] = a1.y;
                ah[mt][2] = a2.x; al[mt][2] = a2.y;
                ah[mt][3] = a3.x; al[mt][3] = a3.y;
            }
#pragma unroll
            for (int nt = 0; nt < 4; nt++) {
                int c = wn * 32 + nt * 8 + gid;
                uint2 b0 = *(uint2*)&sB[(kp0 + tg) * GBP + 2 * c];
                uint2 b1 = *(uint2*)&sB[(kp0 + 4 + tg) * GBP + 2 * c];
#pragma unroll
                for (int mt = 0; mt < 4; mt++)
                    mma3(acc[mt][nt], ah[mt], al[mt], b0.x, b1.x, b0.y, b1.y);
            }
        }
        __syncthreads();
    }
}

// ---------------------------------------------------------------------------
// Fused QKV projection. z = 0/1/2 -> Q/K/V. C in [B,H,N,DH]; Q scaled 1/8.
// ---------------------------------------------------------------------------
__global__ __launch_bounds__(256) void mma_gemm_qkv(
    const float* __restrict__ Xq, const float* __restrict__ Xk,
    const float* __restrict__ Xv, const float* __restrict__ Wq,
    const float* __restrict__ Wk, const float* __restrict__ Wv)
{
    __shared__ __align__(16) uint32_t sA[128 * GAP];
    __shared__ __align__(16) uint32_t sB[16 * GBP];

    const int which = blockIdx.z;
    const float* A = (which == 0) ? Xq : (which == 1) ? Xk : Xv;
    const float* W = (which == 0) ? Wq : (which == 1) ? Wk : Wv;
    float* C = (which == 0) ? g_q : (which == 1) ? g_k : g_v;
    const float sc = (which == 0) ? 0.125f : 1.0f;

    const int bm = blockIdx.x * 128;
    const int bn = blockIdx.y * 128;
    float acc[4][4][4];
#pragma unroll
    for (int mt = 0; mt < 4; mt++)
#pragma unroll
        for (int nt = 0; nt < 4; nt++)
#pragma unroll
            for (int c = 0; c < 4; c++) acc[mt][nt][c] = 0.f;

    gemm_mainloop(A, W, bm, bn, sA, sB, acc);

    const int lane = threadIdx.x & 31;
    const int warp = threadIdx.x >> 5;
    const int gid = lane >> 2, tg = lane & 3;
    const int wm = warp >> 2, wn = warp & 3;

#pragma unroll
    for (int mt = 0; mt < 4; mt++) {
        int row = bm + wm * 64 + mt * 16 + gid;
#pragma unroll
        for (int nt = 0; nt < 4; nt++) {
            int col = bn + wn * 32 + nt * 8 + 2 * tg;
            int h = col >> 6, d = col & 63;
#pragma unroll
            for (int half = 0; half < 2; half++) {
                int r = row + half * 8;
                int b = r >> 11, n = r & 2047;
                float2 v = make_float2(acc[mt][nt][2 * half] * sc,
                                       acc[mt][nt][2 * half + 1] * sc);
                *(float2*)&C[(((size_t)(b * HEADS + h) * NSEQ) + n) * DHEAD + d] = v;
            }
        }
    }
}

// ---------------------------------------------------------------------------
// Wo projection: g_proj = g_attn @ Wo + bo
// ---------------------------------------------------------------------------
__global__ __launch_bounds__(256) void mma_gemm_wo(
    const float* __restrict__ W, const float* __restrict__ bo)
{
    __shared__ __align__(16) uint32_t sA[128 * GAP];
    __shared__ __align__(16) uint32_t sB[16 * GBP];

    const int bm = blockIdx.x * 128;
    const int bn = blockIdx.y * 128;
    float acc[4][4][4];
#pragma unroll
    for (int mt = 0; mt < 4; mt++)
#pragma unroll
        for (int nt = 0; nt < 4; nt++)
#pragma unroll
            for (int c = 0; c < 4; c++) acc[mt][nt][c] = 0.f;

    gemm_mainloop(g_attn, W, bm, bn, sA, sB, acc);

    const int lane = threadIdx.x & 31;
    const int warp = threadIdx.x >> 5;
    const int gid = lane >> 2, tg = lane & 3;
    const int wm = warp >> 2, wn = warp & 3;

#pragma unroll
    for (int mt = 0; mt < 4; mt++) {
        int row = bm + wm * 64 + mt * 16 + gid;
#pragma unroll
        for (int nt = 0; nt < 4; nt++) {
            int col = bn + wn * 32 + nt * 8 + 2 * tg;
            float b0 = bo[col], b1 = bo[col + 1];
#pragma unroll
            for (int half = 0; half < 2; half++) {
                int r = row + half * 8;
                float2 v = make_float2(acc[mt][nt][2 * half] + b0,
                                       acc[mt][nt][2 * half + 1] + b1);
                *(float2*)&g_proj[(size_t)r * DIMC + col] = v;
            }
        }
    }
}

// ---------------------------------------------------------------------------
// Flash attention. Grid: (N/128, B*H), 256 threads (8 warps).
// Warp owns 16 q rows. KV tiles of 64. P in registers. Interleaved hi/lo:
//   sQ [128][72 words], sK [64][72], sV [32 kvp][136]  = 71 KB, 2 CTAs/SM.
// ---------------------------------------------------------------------------
#define PQ 72
#define PK 72
#define PV 136
#define QW (128 * PQ)
#define KW (64 * PK)
#define VW (32 * PV)
#define ATTN_SMEM ((QW + KW + VW) * 4)

__global__ __launch_bounds__(256, 2) void attn_mma()
{
    extern __shared__ __align__(16) uint32_t smw[];
    uint32_t* sQ = smw;
    uint32_t* sK = sQ + QW;
    uint32_t* sV = sK + KW;

    const int tid = threadIdx.x;
    const int w = tid >> 5;
    const int lane = tid & 31;
    const int gid = lane >> 2, tg = lane & 3;
    const int qt = blockIdx.x;
    const int bh = blockIdx.y;

    const float* Qg = g_q + (size_t)bh * NSEQ * DHEAD + qt * 128 * DHEAD;
    const float* Kg = g_k + (size_t)bh * NSEQ * DHEAD;
    const float* Vg = g_v + (size_t)bh * NSEQ * DHEAD;

    // ---- load Q (already scaled) ----
#pragma unroll
    for (int i = 0; i < 8; i++) {
        int flat = i * 1024 + tid * 4;
        int row = flat >> 6, d = flat & 63;
        float4 v = *(const float4*)(Qg + row * DHEAD + d);
        uint32_t h0, l0, h1, l1;
        split_bf2(v.x, v.y, h0, l0);
        split_bf2(v.z, v.w, h1, l1);
        uint4 u; u.x = h0; u.y = l0; u.z = h1; u.w = l1;
        *(uint4*)&sQ[row * PQ + d] = u;
    }
    __syncthreads();

    // ---- hoist Q fragments ----
    uint32_t qh[4][4], ql[4][4];
#pragma unroll
    for (int ks = 0; ks < 4; ks++) {
        const int kp0 = ks * 8;
        const int r = w * 16 + gid;
        uint2 u0 = *(uint2*)&sQ[r * PQ + 2 * (kp0 + tg)];
        uint2 u1 = *(uint2*)&sQ[(r + 8) * PQ + 2 * (kp0 + tg)];
        uint2 u2 = *(uint2*)&sQ[r * PQ + 2 * (kp0 + 4 + tg)];
        uint2 u3 = *(uint2*)&sQ[(r + 8) * PQ + 2 * (kp0 + 4 + tg)];
        qh[ks][0] = u0.x; ql[ks][0] = u0.y;
        qh[ks][1] = u1.x; ql[ks][1] = u1.y;
        qh[ks][2] = u2.x; ql[ks][2] = u2.y;
        qh[ks][3] = u3.x; ql[ks][3] = u3.y;
    }

    float m_[2], l_[2], o[8][4];
#pragma unroll
    for (int h = 0; h < 2; h++) { m_[h] = -1e30f; l_[h] = 0.f; }
#pragma unroll
    for (int nt = 0; nt < 8; nt++)
#pragma unroll
        for (int c = 0; c < 4; c++) o[nt][c] = 0.f;

    for (int kt = 0; kt < NSEQ / 64; kt++) {
        __syncthreads();
        // ---- K tile ----
#pragma unroll
        for (int i = 0; i < 4; i++) {
            int flat = i * 1024 + tid * 4;
            int kv = flat >> 6, d = flat & 63;
            float4 v = *(const float4*)(Kg + (kt * 64 + kv) * DHEAD + d);
            uint32_t h0, l0, h1, l1;
            split_bf2(v.x, v.y, h0, l0);
            split_bf2(v.z, v.w, h1, l1);
            uint4 u; u.x = h0; u.y = l0; u.z = h1; u.w = l1;
            *(uint4*)&sK[kv * PK + d] = u;
        }
        // ---- V tile: pairs along kv ----
#pragma unroll
        for (int i = 0; i < 2; i++) {
            int task = i * 256 + tid;
            int kvp = task >> 4, d0 = (task & 15) * 4;
            float4 v0 = *(const float4*)(Vg + (kt * 64 + 2 * kvp) * DHEAD + d0);
            float4 v1 = *(const float4*)(Vg + (kt * 64 + 2 * kvp + 1) * DHEAD + d0);
            uint32_t h0, l0, h1, l1, h2, l2, h3, l3;
            split_bf2(v0.x, v1.x, h0, l0);
            split_bf2(v0.y, v1.y, h1, l1);
            split_bf2(v0.z, v1.z, h2, l2);
            split_bf2(v0.w, v1.w, h3, l3);
            uint4 ua; ua.x = h0; ua.y = l0; ua.z = h1; ua.w = l1;
            uint4 ub; ub.x = h2; ub.y = l2; ub.z = h3; ub.w = l3;
            *(uint4*)&sV[kvp * PV + 2 * d0]     = ua;
            *(uint4*)&sV[kvp * PV + 2 * d0 + 4] = ub;
        }
        __syncthreads();

        // ---- S = Q @ K^T ----
        float s[8][4];
#pragma unroll
        for (int nt = 0; nt < 8; nt++)
#pragma unroll
            for (int c = 0; c < 4; c++) s[nt][c] = 0.f;

#pragma unroll
        for (int ks = 0; ks < 4; ks++) {
            const int kp0 = ks * 8;
#pragma unroll
            for (int nt = 0; nt < 8; nt++) {
                int c = nt * 8 + gid;
                uint2 k0 = *(uint2*)&sK[c * PK + 2 * (kp0 + tg)];
                uint2 k1 = *(uint2*)&sK[c * PK + 2 * (kp0 + 4 + tg)];
                mma3(s[nt], qh[ks], ql[ks], k0.x, k1.x, k0.y, k1.y);
            }
        }

        // ---- online softmax ----
#pragma unroll
        for (int h = 0; h < 2; h++) {
            float mx = -1e30f;
#pragma unroll
            for (int nt = 0; nt < 8; nt++)
                mx = fmaxf(mx, fmaxf(s[nt][2 * h], s[nt][2 * h + 1]));
            mx = fmaxf(mx, __shfl_xor_sync(0xffffffffu, mx, 1));
            mx = fmaxf(mx, __shfl_xor_sync(0xffffffffu, mx, 2));
            float mnew = fmaxf(m_[h], mx);
            float corr = __expf(m_[h] - mnew);
            m_[h] = mnew;
            float rs = 0.f;
#pragma unroll
            for (int nt = 0; nt < 8; nt++) {
                float p0 = __expf(s[nt][2 * h] - mnew);
                float p1 = __expf(s[nt][2 * h + 1] - mnew);
                s[nt][2 * h] = p0;
                s[nt][2 * h + 1] = p1;
                rs += p0 + p1;
            }
            rs += __shfl_xor_sync(0xffffffffu, rs, 1);
            rs += __shfl_xor_sync(0xffffffffu, rs, 2);
            l_[h] = l_[h] * corr + rs;
#pragma unroll
            for (int nt = 0; nt < 8; nt++) {
                o[nt][2 * h] *= corr;
                o[nt][2 * h + 1] *= corr;
            }
        }

        // ---- O += P @ V ----
#pragma unroll
        for (int ks = 0; ks < 4; ks++) {
            uint32_t pah[4], pal[4];
            split_bf2(s[2 * ks][0],     s[2 * ks][1],     pah[0], pal[0]);
            split_bf2(s[2 * ks][2],     s[2 * ks][3],     pah[1], pal[1]);
            split_bf2(s[2 * ks + 1][0], s[2 * ks + 1][1], pah[2], pal[2]);
            split_bf2(s[2 * ks + 1][2], s[2 * ks + 1][3], pah[3], pal[3]);
            const int kp0 = ks * 8;
#pragma unroll
            for (int nt = 0; nt < 8; nt++) {
                int d = nt * 8 + gid;
                uint2 v0 = *(uint2*)&sV[(kp0 + tg) * PV + 2 * d];
                uint2 v1 = *(uint2*)&sV[(kp0 + 4 + tg) * PV + 2 * d];
                mma3(o[nt], pah, pal, v0.x, v1.x, v0.y, v1.y);
            }
        }
    }

    // ---- epilogue ----
    const int b = bh >> 4;
    const int hh = bh & 15;
#pragma unroll
    for (int h = 0; h < 2; h++) {
        float inv = 1.0f / l_[h];
        int n = qt * 128 + w * 16 + gid + h * 8;
#pragma unroll
        for (int nt = 0; nt < 8; nt++) {
            int col = hh * DHEAD + nt * 8 + 2 * tg;
            float2 v = make_float2(o[nt][2 * h] * inv, o[nt][2 * h + 1] * inv);
            *(float2*)&g_attn[((size_t)b * NSEQ + n) * DIMC + col] = v;
        }
    }
}

// ---------------------------------------------------------------------------
// LayerNorm over last dim + residual. One block per row.
// ---------------------------------------------------------------------------
__global__ __launch_bounds__(256) void ln_kernel(
    const float* __restrict__ query, const float* __restrict__ gamma,
    const float* __restrict__ beta, float* __restrict__ out)
{
    const int r = blockIdx.x;
    const float* x = g_proj + (size_t)r * DIMC;

    float v[4];
    float s = 0.f, ss = 0.f;
#pragma unroll
    for (int i = 0; i < 4; i++) {
        v[i] = x[threadIdx.x + 256 * i];
        s += v[i];
        ss += v[i] * v[i];
    }
#pragma unroll
    for (int ofs = 16; ofs > 0; ofs >>= 1) {
        s  += __shfl_xor_sync(0xffffffffu, s,  ofs);
        ss += __shfl_xor_sync(0xffffffffu, ss, ofs);
    }
    __shared__ float rs[8], rss[8];
    int w = threadIdx.x >> 5, lane = threadIdx.x & 31;
    if (lane == 0) { rs[w] = s; rss[w] = ss; }
    __syncthreads();
    if (threadIdx.x == 0) {
        float a = 0.f, b2 = 0.f;
#pragma unroll
        for (int i = 0; i < 8; i++) { a += rs[i]; b2 += rss[i]; }
        rs[0] = a; rss[0] = b2;
    }
    __syncthreads();
    const float mean = rs[0] * (1.0f / DIMC);
    const float var  = rss[0] * (1.0f / DIMC) - mean * mean;
    const float inv  = rsqrtf(var + 1e-5f);

#pragma unroll
    for (int i = 0; i < 4; i++) {
        int c = threadIdx.x + 256 * i;
        size_t idx = (size_t)r * DIMC + c;
        out[idx] = (v[i] - mean) * inv * gamma[c] + beta[c] + query[idx];
    }
}

// ---------------------------------------------------------------------------
extern "C" void kernel_launch(void* const* d_in, const int* in_sizes, int n_in,
                              void* d_out, int out_size)
{
    const float* query = (const float*)d_in[0];
    const float* key_  = (const float*)d_in[1];
    const float* value = (const float*)d_in[2];
    const float* Wq    = (const float*)d_in[3];
    const float* Wk    = (const float*)d_in[4];
    const float* Wv    = (const float*)d_in[5];
    const float* Wo    = (const float*)d_in[6];
    const float* bo    = (const float*)d_in[7];
    const float* gamma = (const float*)d_in[8];
    const float* beta  = (const float*)d_in[9];
    float* out = (float*)d_out;

    cudaFuncSetAttribute(attn_mma,
                         cudaFuncAttributeMaxDynamicSharedMemorySize, ATTN_SMEM);

    // 1) QKV projections (fused launch) -> [B,H,N,DH]
    mma_gemm_qkv<<<dim3(MTOT / 128, DIMC / 128, 3), 256>>>(query, key_, value,
                                                           Wq, Wk, Wv);
    // 2) Attention -> [B,N,H*DH]
    attn_mma<<<dim3(NSEQ / 128, BC * HEADS), 256, ATTN_SMEM>>>();
    // 3) Wo projection + bias
    mma_gemm_wo<<<dim3(MTOT / 128, DIMC / 128), 256>>>(Wo, bo);
    // 4) LayerNorm + residual
    ln_kernel<<<MTOT, 256>>>(query, gamma, beta, out);
}

// round 12
// speedup vs baseline: 1.7178x; 1.7178x over previous
#include <cuda_runtime.h>
#include <cstdint>

// ---------------------------------------------------------------------------
// MultiHeadAttention: out = LN( softmax(QK^T/sqrt(d)) V @ Wo + bo ) + query
// B=4, N=2048, DIM=1024, HEADS=16, DH=64
// Round-11: R9 mma structure + all bf16 hi/lo splits precomputed
// (prep kernels + epilogues). Hot loops: pure LDG/STS/LDS/HMMA.
// ---------------------------------------------------------------------------

#define BC    4
#define NSEQ  2048
#define DIMC  1024
#define HEADS 16
#define DHEAD 64
#define MTOT  (BC * NSEQ)          // 8192
#define XWRD  (MTOT * (DIMC / 2))  // packed words per [8192,1024] tensor
#define WWRD  ((DIMC / 2) * DIMC)  // packed words per [1024,1024] weight

// Packed split scratch (device globals; allocation-free per harness rules)
__device__ uint32_t g_xh[3][XWRD], g_xl[3][XWRD];   // X inputs, pairs along k
__device__ uint32_t g_wh[4][WWRD], g_wl[4][WWRD];   // W, [kp][n] pairs across k
__device__ uint32_t g_qh[XWRD], g_ql[XWRD];         // Q [B,H,N,DH/2], scaled
__device__ uint32_t g_kh[XWRD], g_kl[XWRD];         // K [B,H,N,DH/2]
__device__ float    g_v[MTOT * DIMC];               // V [B,H,N,DH] fp32
__device__ uint32_t g_ah[XWRD], g_al[XWRD];         // attn out [B,N,(H*DH)/2]
__device__ float    g_proj[MTOT * DIMC];            // attn @ Wo + bo

// ---------------------------------------------------------------------------
// bf16 split helpers
// ---------------------------------------------------------------------------
__device__ __forceinline__ uint32_t pack_bf2(float x0, float x1)
{
    uint32_t p;
    asm("cvt.rn.satfinite.bf16x2.f32 %0, %1, %2;" : "=r"(p) : "f"(x1), "f"(x0));
    return p;
}
__device__ __forceinline__ void split_bf2(float x0, float x1,
                                          uint32_t& hi, uint32_t& lo)
{
    uint32_t h = pack_bf2(x0, x1);
    float h0 = __uint_as_float(h << 16);
    float h1 = __uint_as_float(h & 0xffff0000u);
    lo = pack_bf2(x0 - h0, x1 - h1);
    hi = h;
}
__device__ __forceinline__ void mma16(float* d,
                                      uint32_t a0, uint32_t a1, uint32_t a2, uint32_t a3,
                                      uint32_t b0, uint32_t b1)
{
    asm volatile(
        "mma.sync.aligned.m16n8k16.row.col.f32.bf16.bf16.f32 "
        "{%0,%1,%2,%3}, {%4,%5,%6,%7}, {%8,%9}, {%0,%1,%2,%3};\n"
        : "+f"(d[0]), "+f"(d[1]), "+f"(d[2]), "+f"(d[3])
        : "r"(a0), "r"(a1), "r"(a2), "r"(a3), "r"(b0), "r"(b1));
}
// 3-term: D += Ah*Bl + Al*Bh + Ah*Bh
__device__ __forceinline__ void mma3(float* d,
                                     const uint32_t* ah, const uint32_t* al,
                                     uint32_t bh0, uint32_t bh1,
                                     uint32_t bl0, uint32_t bl1)
{
    mma16(d, ah[0], ah[1], ah[2], ah[3], bl0, bl1);
    mma16(d, al[0], al[1], al[2], al[3], bh0, bh1);
    mma16(d, ah[0], ah[1], ah[2], ah[3], bh0, bh1);
}

// ---------------------------------------------------------------------------
// Prep: split X (pairs along k, row-major). grid (MTOT*DIMC/1024, 1, 3)
// ---------------------------------------------------------------------------
__global__ __launch_bounds__(256) void x_prep(
    const float* __restrict__ Xq, const float* __restrict__ Xk,
    const float* __restrict__ Xv)
{
    const int z = blockIdx.z;
    const float* X = (z == 0) ? Xq : (z == 1) ? Xk : Xv;
    uint32_t* oh = g_xh[z];
    uint32_t* ol = g_xl[z];
    int i = blockIdx.x * 256 + threadIdx.x;    // float4 index
    float4 v = ((const float4*)X)[i];
    uint32_t h0, l0, h1, l1;
    split_bf2(v.x, v.y, h0, l0);
    split_bf2(v.z, v.w, h1, l1);
    uint2 uh; uh.x = h0; uh.y = h1;
    uint2 ul; ul.x = l0; ul.y = l1;
    *(uint2*)&oh[2 * i] = uh;
    *(uint2*)&ol[2 * i] = ul;
}

// ---------------------------------------------------------------------------
// Prep: split W into [kp][n] (pairs across k rows). grid (WWRD/1024, 1, 4)
// ---------------------------------------------------------------------------
__global__ __launch_bounds__(256) void w_prep(
    const float* __restrict__ Wq, const float* __restrict__ Wk,
    const float* __restrict__ Wv, const float* __restrict__ Wo)
{
    const int z = blockIdx.z;
    const float* W = (z == 0) ? Wq : (z == 1) ? Wk : (z == 2) ? Wv : Wo;
    uint32_t* oh = g_wh[z];
    uint32_t* ol = g_wl[z];
    int idx = blockIdx.x * 256 + threadIdx.x;  // covers 4 n at one kp
    int kp = idx >> 8;
    int n4 = (idx & 255) * 4;
    float4 a = *(const float4*)(W + (size_t)(2 * kp) * DIMC + n4);
    float4 b = *(const float4*)(W + (size_t)(2 * kp + 1) * DIMC + n4);
    uint32_t hw[4], lw[4];
    split_bf2(a.x, b.x, hw[0], lw[0]);
    split_bf2(a.y, b.y, hw[1], lw[1]);
    split_bf2(a.z, b.z, hw[2], lw[2]);
    split_bf2(a.w, b.w, hw[3], lw[3]);
    *(uint4*)&oh[(size_t)kp * DIMC + n4] = *(uint4*)&hw[0];
    *(uint4*)&ol[(size_t)kp * DIMC + n4] = *(uint4*)&lw[0];
}

// ---------------------------------------------------------------------------
// GEMM mainloop (packed operands): 128x128 block, BK=32 (16 kp), 256 thr.
// sA[128][20], sB[16][136] (hi and lo each) — identical fragment indexing
// to the benched R9 kernel. Loaders are pure copies.
// ---------------------------------------------------------------------------
#define GAP 20
#define GBP 136

__device__ __forceinline__ void gemm_mainloop(
    const uint32_t* __restrict__ Ahg, const uint32_t* __restrict__ Alg,
    const uint32_t* __restrict__ Bhg, const uint32_t* __restrict__ Blg,
    int bm, int bn,
    uint32_t* sAh, uint32_t* sAl, uint32_t* sBh, uint32_t* sBl,
    float acc[4][4][4])
{
    const int tid = threadIdx.x;
    const int lane = tid & 31;
    const int warp = tid >> 5;
    const int gid = lane >> 2;
    const int tg = lane & 3;
    const int wm = warp >> 2;   // 0..1
    const int wn = warp & 3;    // 0..3

    uint4 pah[2], pal[2], pbh[2], pbl[2];
#pragma unroll
    for (int i = 0; i < 2; i++) {
        int fw = i * 1024 + tid * 4;
        int arow = fw >> 4, akp = fw & 15;
        int bkp = fw >> 7, bnn = fw & 127;
        size_t ga = (size_t)(bm + arow) * 512 + akp;
        size_t gb = (size_t)bkp * DIMC + bn + bnn;
        pah[i] = *(const uint4*)&Ahg[ga];
        pal[i] = *(const uint4*)&Alg[ga];
        pbh[i] = *(const uint4*)&Bhg[gb];
        pbl[i] = *(const uint4*)&Blg[gb];
    }

    for (int kb = 0; kb < 32; kb++) {
#pragma unroll
        for (int i = 0; i < 2; i++) {
            int fw = i * 1024 + tid * 4;
            int arow = fw >> 4, akp = fw & 15;
            int bkp = fw >> 7, bnn = fw & 127;
            *(uint4*)&sAh[arow * GAP + akp] = pah[i];
            *(uint4*)&sAl[arow * GAP + akp] = pal[i];
            *(uint4*)&sBh[bkp * GBP + bnn] = pbh[i];
            *(uint4*)&sBl[bkp * GBP + bnn] = pbl[i];
        }
        __syncthreads();

        if (kb < 31) {
            int k0 = (kb + 1) * 16;
#pragma unroll
            for (int i = 0; i < 2; i++) {
                int fw = i * 1024 + tid * 4;
                int arow = fw >> 4, akp = fw & 15;
                int bkp = fw >> 7, bnn = fw & 127;
                size_t ga = (size_t)(bm + arow) * 512 + k0 + akp;
                size_t gb = (size_t)(k0 + bkp) * DIMC + bn + bnn;
                pah[i] = *(const uint4*)&Ahg[ga];
                pal[i] = *(const uint4*)&Alg[ga];
                pbh[i] = *(const uint4*)&Bhg[gb];
                pbl[i] = *(const uint4*)&Blg[gb];
            }
        }

#pragma unroll
        for (int ks = 0; ks < 2; ks++) {
            const int kp0 = ks * 8;
            uint32_t ah[4][4], al[4][4];
#pragma unroll
            for (int mt = 0; mt < 4; mt++) {
                int r = wm * 64 + mt * 16 + gid;
                ah[mt][0] = sAh[r * GAP + kp0 + tg];
                ah[mt][1] = sAh[(r + 8) * GAP + kp0 + tg];
                ah[mt][2] = sAh[r * GAP + kp0 + 4 + tg];
                ah[mt][3] = sAh[(r + 8) * GAP + kp0 + 4 + tg];
                al[mt][0] = sAl[r * GAP + kp0 + tg];
                al[mt][1] = sAl[(r + 8) * GAP + kp0 + tg];
                al[mt][2] = sAl[r * GAP + kp0 + 4 + tg];
                al[mt][3] = sAl[(r + 8) * GAP + kp0 + 4 + tg];
            }
#pragma unroll
            for (int nt = 0; nt < 4; nt++) {
                int c = wn * 32 + nt * 8 + gid;
                uint32_t bh0 = sBh[(kp0 + tg) * GBP + c];
                uint32_t bh1 = sBh[(kp0 + 4 + tg) * GBP + c];
                uint32_t bl0 = sBl[(kp0 + tg) * GBP + c];
                uint32_t bl1 = sBl[(kp0 + 4 + tg) * GBP + c];
#pragma unroll
                for (int mt = 0; mt < 4; mt++)
                    mma3(acc[mt][nt], ah[mt], al[mt], bh0, bh1, bl0, bl1);
            }
        }
        __syncthreads();
    }
}

// ---------------------------------------------------------------------------
// QKV projection. which 0/1/2 -> Q/K/V. Q/K epilogues emit packed bf16 hi/lo
// in [B,H,N,DH/2]; Q pre-scaled by 1/8. V emits fp32 [B,H,N,DH].
// ---------------------------------------------------------------------------
__global__ __launch_bounds__(256) void mma_gemm_qkv(int which)
{
    __shared__ __align__(16) uint32_t sAh[128 * GAP], sAl[128 * GAP];
    __shared__ __align__(16) uint32_t sBh[16 * GBP], sBl[16 * GBP];

    const int bm = blockIdx.x * 128;
    const int bn = blockIdx.y * 128;
    float acc[4][4][4];
#pragma unroll
    for (int mt = 0; mt < 4; mt++)
#pragma unroll
        for (int nt = 0; nt < 4; nt++)
#pragma unroll
            for (int c = 0; c < 4; c++) acc[mt][nt][c] = 0.f;

    gemm_mainloop(g_xh[which], g_xl[which], g_wh[which], g_wl[which],
                  bm, bn, sAh, sAl, sBh, sBl, acc);

    const int lane = threadIdx.x & 31;
    const int warp = threadIdx.x >> 5;
    const int gid = lane >> 2, tg = lane & 3;
    const int wm = warp >> 2, wn = warp & 3;

    if (which < 2) {
        const float sc = (which == 0) ? 0.125f : 1.0f;
        uint32_t* Ch = (which == 0) ? g_qh : g_kh;
        uint32_t* Cl = (which == 0) ? g_ql : g_kl;
#pragma unroll
        for (int mt = 0; mt < 4; mt++) {
            int row = bm + wm * 64 + mt * 16 + gid;
#pragma unroll
            for (int nt = 0; nt < 4; nt++) {
                int col = bn + wn * 32 + nt * 8 + 2 * tg;
                int h = col >> 6, dp = (col & 63) >> 1;
#pragma unroll
                for (int half = 0; half < 2; half++) {
                    int r = row + half * 8;
                    int b = r >> 11, n = r & 2047;
                    uint32_t hw, lw;
                    split_bf2(acc[mt][nt][2 * half] * sc,
                              acc[mt][nt][2 * half + 1] * sc, hw, lw);
                    size_t wi = ((size_t)(b * HEADS + h) * NSEQ + n) * 32 + dp;
                    Ch[wi] = hw;
                    Cl[wi] = lw;
                }
            }
        }
    } else {
#pragma unroll
        for (int mt = 0; mt < 4; mt++) {
            int row = bm + wm * 64 + mt * 16 + gid;
#pragma unroll
            for (int nt = 0; nt < 4; nt++) {
                int col = bn + wn * 32 + nt * 8 + 2 * tg;
                int h = col >> 6, d = col & 63;
#pragma unroll
                for (int half = 0; half < 2; half++) {
                    int r = row + half * 8;
                    int b = r >> 11, n = r & 2047;
                    float2 v = make_float2(acc[mt][nt][2 * half],
                                           acc[mt][nt][2 * half + 1]);
                    *(float2*)&g_v[(((size_t)(b * HEADS + h) * NSEQ) + n) * DHEAD + d] = v;
                }
            }
        }
    }
}

// ---------------------------------------------------------------------------
// Wo projection: g_proj = attn_packed @ Wo + bo  (fp32 out for LN)
// ---------------------------------------------------------------------------
__global__ __launch_bounds__(256) void mma_gemm_wo(const float* __restrict__ bo)
{
    __shared__ __align__(16) uint32_t sAh[128 * GAP], sAl[128 * GAP];
    __shared__ __align__(16) uint32_t sBh[16 * GBP], sBl[16 * GBP];

    const int bm = blockIdx.x * 128;
    const int bn = blockIdx.y * 128;
    float acc[4][4][4];
#pragma unroll
    for (int mt = 0; mt < 4; mt++)
#pragma unroll
        for (int nt = 0; nt < 4; nt++)
#pragma unroll
            for (int c = 0; c < 4; c++) acc[mt][nt][c] = 0.f;

    gemm_mainloop(g_ah, g_al, g_wh[3], g_wl[3], bm, bn, sAh, sAl, sBh, sBl, acc);

    const int lane = threadIdx.x & 31;
    const int warp = threadIdx.x >> 5;
    const int gid = lane >> 2, tg = lane & 3;
    const int wm = warp >> 2, wn = warp & 3;

#pragma unroll
    for (int mt = 0; mt < 4; mt++) {
        int row = bm + wm * 64 + mt * 16 + gid;
#pragma unroll
        for (int nt = 0; nt < 4; nt++) {
            int col = bn + wn * 32 + nt * 8 + 2 * tg;
            float b0 = bo[col], b1 = bo[col + 1];
#pragma unroll
            for (int half = 0; half < 2; half++) {
                int r = row + half * 8;
                float2 v = make_float2(acc[mt][nt][2 * half] + b0,
                                       acc[mt][nt][2 * half + 1] + b1);
                *(float2*)&g_proj[(size_t)r * DIMC + col] = v;
            }
        }
    }
}

// ---------------------------------------------------------------------------
// Flash attention (R9 structure). Grid: (N/128, B*H), 256 threads (8 warps).
// Q/K loaders: pure copies of packed operands. V: fp32 + split (seq pairs).
// smem: sQ hi/lo [128][36], sK hi/lo [64][36], sV hi/lo [32][72] = 72 KB.
// ---------------------------------------------------------------------------
#define AQP 36
#define AKP 36
#define AVP 72
#define QW  (128 * AQP)
#define KW  (64 * AKP)
#define VW  (32 * AVP)
#define ATTN_SMEM ((2 * (QW + KW + VW)) * 4)

__global__ __launch_bounds__(256, 2) void attn_mma()
{
    extern __shared__ __align__(16) uint32_t smw[];
    uint32_t* sQh = smw;
    uint32_t* sQl = sQh + QW;
    uint32_t* sKh = sQl + QW;
    uint32_t* sKl = sKh + KW;
    uint32_t* sVh = sKl + KW;
    uint32_t* sVl = sVh + VW;

    const int tid = threadIdx.x;
    const int w = tid >> 5;
    const int lane = tid & 31;
    const int gid = lane >> 2, tg = lane & 3;
    const int qt = blockIdx.x;
    const int bh = blockIdx.y;

    const size_t rowbase = (size_t)bh * NSEQ * 32;   // packed words per row = 32
    const float* Vg = g_v + (size_t)bh * NSEQ * DHEAD;

    // ---- load Q tile: pure copy (already scaled + split) ----
    {
        const size_t qbase = rowbase + (size_t)qt * 128 * 32;
#pragma unroll
        for (int i = 0; i < 4; i++) {
            int fw = i * 1024 + tid * 4;
            int row = fw >> 5, kpo = fw & 31;
            uint4 h = *(const uint4*)&g_qh[qbase + fw];
            uint4 l = *(const uint4*)&g_ql[qbase + fw];
            *(uint4*)&sQh[row * AQP + kpo] = h;
            *(uint4*)&sQl[row * AQP + kpo] = l;
        }
    }
    __syncthreads();

    // ---- hoist Q fragments for this warp's 16 rows ----
    uint32_t qh[4][4], ql[4][4];
#pragma unroll
    for (int ks = 0; ks < 4; ks++) {
        const int kp0 = ks * 8;
        const int r = w * 16 + gid;
        qh[ks][0] = sQh[r * AQP + kp0 + tg];
        qh[ks][1] = sQh[(r + 8) * AQP + kp0 + tg];
        qh[ks][2] = sQh[r * AQP + kp0 + 4 + tg];
        qh[ks][3] = sQh[(r + 8) * AQP + kp0 + 4 + tg];
        ql[ks][0] = sQl[r * AQP + kp0 + tg];
        ql[ks][1] = sQl[(r + 8) * AQP + kp0 + tg];
        ql[ks][2] = sQl[r * AQP + kp0 + 4 + tg];
        ql[ks][3] = sQl[(r + 8) * AQP + kp0 + 4 + tg];
    }

    float m_[2], l_[2], o[8][4];
#pragma unroll
    for (int h = 0; h < 2; h++) { m_[h] = -1e30f; l_[h] = 0.f; }
#pragma unroll
    for (int nt = 0; nt < 8; nt++)
#pragma unroll
        for (int c = 0; c < 4; c++) o[nt][c] = 0.f;

    for (int kt = 0; kt < NSEQ / 64; kt++) {
        __syncthreads();
        // ---- K tile: pure copy ----
        {
            const size_t kb = rowbase + (size_t)kt * 64 * 32;
#pragma unroll
            for (int i = 0; i < 2; i++) {
                int fw = i * 1024 + tid * 4;
                int kv = fw >> 5, kpo = fw & 31;
                uint4 h = *(const uint4*)&g_kh[kb + fw];
                uint4 l = *(const uint4*)&g_kl[kb + fw];
                *(uint4*)&sKh[kv * AKP + kpo] = h;
                *(uint4*)&sKl[kv * AKP + kpo] = l;
            }
        }
        // ---- V tile: fp32 + split (pairs along kv) ----
#pragma unroll
        for (int i = 0; i < 2; i++) {
            int task = i * 256 + tid;
            int kvp = task >> 4, d0 = (task & 15) * 4;
            float4 v0 = *(const float4*)(Vg + (kt * 64 + 2 * kvp) * DHEAD + d0);
            float4 v1 = *(const float4*)(Vg + (kt * 64 + 2 * kvp + 1) * DHEAD + d0);
            uint32_t hh[4], ll[4];
            split_bf2(v0.x, v1.x, hh[0], ll[0]);
            split_bf2(v0.y, v1.y, hh[1], ll[1]);
            split_bf2(v0.z, v1.z, hh[2], ll[2]);
            split_bf2(v0.w, v1.w, hh[3], ll[3]);
            *(uint4*)&sVh[kvp * AVP + d0] = *(uint4*)&hh[0];
            *(uint4*)&sVl[kvp * AVP + d0] = *(uint4*)&ll[0];
        }
        __syncthreads();

        // ---- S = Q @ K^T ----
        float s[8][4];
#pragma unroll
        for (int nt = 0; nt < 8; nt++)
#pragma unroll
            for (int c = 0; c < 4; c++) s[nt][c] = 0.f;

#pragma unroll
        for (int ks = 0; ks < 4; ks++) {
            const int kp0 = ks * 8;
#pragma unroll
            for (int nt = 0; nt < 8; nt++) {
                int c = nt * 8 + gid;
                uint32_t bh0 = sKh[c * AKP + kp0 + tg];
                uint32_t bh1 = sKh[c * AKP + kp0 + 4 + tg];
                uint32_t bl0 = sKl[c * AKP + kp0 + tg];
                uint32_t bl1 = sKl[c * AKP + kp0 + 4 + tg];
                mma3(s[nt], qh[ks], ql[ks], bh0, bh1, bl0, bl1);
            }
        }

        // ---- online softmax ----
#pragma unroll
        for (int h = 0; h < 2; h++) {
            float mx = -1e30f;
#pragma unroll
            for (int nt = 0; nt < 8; nt++)
                mx = fmaxf(mx, fmaxf(s[nt][2 * h], s[nt][2 * h + 1]));
            mx = fmaxf(mx, __shfl_xor_sync(0xffffffffu, mx, 1));
            mx = fmaxf(mx, __shfl_xor_sync(0xffffffffu, mx, 2));
            float mnew = fmaxf(m_[h], mx);
            float corr = __expf(m_[h] - mnew);
            m_[h] = mnew;
            float rs = 0.f;
#pragma unroll
            for (int nt = 0; nt < 8; nt++) {
                float p0 = __expf(s[nt][2 * h] - mnew);
                float p1 = __expf(s[nt][2 * h + 1] - mnew);
                s[nt][2 * h] = p0;
                s[nt][2 * h + 1] = p1;
                rs += p0 + p1;
            }
            rs += __shfl_xor_sync(0xffffffffu, rs, 1);
            rs += __shfl_xor_sync(0xffffffffu, rs, 2);
            l_[h] = l_[h] * corr + rs;
#pragma unroll
            for (int nt = 0; nt < 8; nt++) {
                o[nt][2 * h] *= corr;
                o[nt][2 * h + 1] *= corr;
            }
        }

        // ---- O += P @ V ----
#pragma unroll
        for (int ks = 0; ks < 4; ks++) {
            uint32_t pah[4], pal[4];
            split_bf2(s[2 * ks][0],     s[2 * ks][1],     pah[0], pal[0]);
            split_bf2(s[2 * ks][2],     s[2 * ks][3],     pah[1], pal[1]);
            split_bf2(s[2 * ks + 1][0], s[2 * ks + 1][1], pah[2], pal[2]);
            split_bf2(s[2 * ks + 1][2], s[2 * ks + 1][3], pah[3], pal[3]);
            const int kp0 = ks * 8;
#pragma unroll
            for (int nt = 0; nt < 8; nt++) {
                int d = nt * 8 + gid;
                uint32_t bh0 = sVh[(kp0 + tg) * AVP + d];
                uint32_t bh1 = sVh[(kp0 + 4 + tg) * AVP + d];
                uint32_t bl0 = sVl[(kp0 + tg) * AVP + d];
                uint32_t bl1 = sVl[(kp0 + 4 + tg) * AVP + d];
                mma3(o[nt], pah, pal, bh0, bh1, bl0, bl1);
            }
        }
    }

    // ---- epilogue: normalize + split + write packed [B,N,(H*DH)/2] ----
    const int b = bh >> 4;
    const int hh = bh & 15;
#pragma unroll
    for (int h = 0; h < 2; h++) {
        float inv = 1.0f / l_[h];
        int n = qt * 128 + w * 16 + gid + h * 8;
        size_t rw = (size_t)(b * NSEQ + n) * 512;
#pragma unroll
        for (int nt = 0; nt < 8; nt++) {
            int cp = hh * 32 + nt * 4 + tg;   // (col)/2
            uint32_t hw, lw;
            split_bf2(o[nt][2 * h] * inv, o[nt][2 * h + 1] * inv, hw, lw);
            g_ah[rw + cp] = hw;
            g_al[rw + cp] = lw;
        }
    }
}

// ---------------------------------------------------------------------------
// LayerNorm over last dim + residual. One block per row.
// ---------------------------------------------------------------------------
__global__ __launch_bounds__(256) void ln_kernel(
    const float* __restrict__ query, const float* __restrict__ gamma,
    const float* __restrict__ beta, float* __restrict__ out)
{
    const int r = blockIdx.x;
    const float* x = g_proj + (size_t)r * DIMC;

    float v[4];
    float s = 0.f, ss = 0.f;
#pragma unroll
    for (int i = 0; i < 4; i++) {
        v[i] = x[threadIdx.x + 256 * i];
        s += v[i];
        ss += v[i] * v[i];
    }
#pragma unroll
    for (int ofs = 16; ofs > 0; ofs >>= 1) {
        s  += __shfl_xor_sync(0xffffffffu, s,  ofs);
        ss += __shfl_xor_sync(0xffffffffu, ss, ofs);
    }
    __shared__ float rs[8], rss[8];
    int w = threadIdx.x >> 5, lane = threadIdx.x & 31;
    if (lane == 0) { rs[w] = s; rss[w] = ss; }
    __syncthreads();
    if (threadIdx.x == 0) {
        float a = 0.f, b2 = 0.f;
#pragma unroll
        for (int i = 0; i < 8; i++) { a += rs[i]; b2 += rss[i]; }
        rs[0] = a; rss[0] = b2;
    }
    __syncthreads();
    const float mean = rs[0] * (1.0f / DIMC);
    const float var  = rss[0] * (1.0f / DIMC) - mean * mean;
    const float inv  = rsqrtf(var + 1e-5f);

#pragma unroll
    for (int i = 0; i < 4; i++) {
        int c = threadIdx.x + 256 * i;
        size_t idx = (size_t)r * DIMC + c;
        out[idx] = (v[i] - mean) * inv * gamma[c] + beta[c] + query[idx];
    }
}

// ---------------------------------------------------------------------------
extern "C" void kernel_launch(void* const* d_in, const int* in_sizes, int n_in,
                              void* d_out, int out_size)
{
    const float* query = (const float*)d_in[0];
    const float* key_  = (const float*)d_in[1];
    const float* value = (const float*)d_in[2];
    const float* Wq    = (const float*)d_in[3];
    const float* Wk    = (const float*)d_in[4];
    const float* Wv    = (const float*)d_in[5];
    const float* Wo    = (const float*)d_in[6];
    const float* bo    = (const float*)d_in[7];
    const float* gamma = (const float*)d_in[8];
    const float* beta  = (const float*)d_in[9];
    float* out = (float*)d_out;

    cudaFuncSetAttribute(attn_mma,
                         cudaFuncAttributeMaxDynamicSharedMemorySize, ATTN_SMEM);

    // 0) split prep
    x_prep<<<dim3(MTOT * DIMC / 1024, 1, 3), 256>>>(query, key_, value);
    w_prep<<<dim3(WWRD / 1024, 1, 4), 256>>>(Wq, Wk, Wv, Wo);

    dim3 ggrid(MTOT / 128, DIMC / 128);
    // 1) QKV projections
    mma_gemm_qkv<<<ggrid, 256>>>(0);
    mma_gemm_qkv<<<ggrid, 256>>>(1);
    mma_gemm_qkv<<<ggrid, 256>>>(2);
    // 2) Attention
    attn_mma<<<dim3(NSEQ / 128, BC * HEADS), 256, ATTN_SMEM>>>();
    // 3) Wo projection + bias
    mma_gemm_wo<<<ggrid, 256>>>(bo);
    // 4) LayerNorm + residual
    ln_kernel<<<MTOT, 256>>>(query, gamma, beta, out);
}

// round 16
// speedup vs baseline: 1.9924x; 1.1598x over previous
#include <cuda_runtime.h>
#include <cstdint>

// ---------------------------------------------------------------------------
// MultiHeadAttention: out = LN( softmax(QK^T/sqrt(d)) V @ Wo + bo ) + query
// B=4, N=2048, DIM=1024, HEADS=16, DH=64
// Round-14: R11 (packed pre-split bf16 operands) + cp.async double-buffered
// GEMM at 2 CTAs/SM. No tcgen05 (harness PTX target rejects it).
// ---------------------------------------------------------------------------

#define BC    4
#define NSEQ  2048
#define DIMC  1024
#define HEADS 16
#define DHEAD 64
#define MTOT  (BC * NSEQ)          // 8192
#define XWRD  (MTOT * (DIMC / 2))
#define WWRD  ((DIMC / 2) * DIMC)

__device__ uint32_t g_xh[3][XWRD], g_xl[3][XWRD];   // X inputs, [m][kp]
__device__ uint32_t g_wh[4][WWRD], g_wl[4][WWRD];   // W, [kp][n]
__device__ uint32_t g_qh[XWRD], g_ql[XWRD];         // Q packed, scaled 1/8
__device__ uint32_t g_kh[XWRD], g_kl[XWRD];         // K packed
__device__ float    g_v[MTOT * DIMC];               // V fp32 [B,H,N,DH]
__device__ uint32_t g_ah[XWRD], g_al[XWRD];         // attn out packed
__device__ float    g_proj[MTOT * DIMC];

// ---------------------------------------------------------------------------
__device__ __forceinline__ uint32_t pack_bf2(float x0, float x1)
{
    uint32_t p;
    asm("cvt.rn.satfinite.bf16x2.f32 %0, %1, %2;" : "=r"(p) : "f"(x1), "f"(x0));
    return p;
}
__device__ __forceinline__ void split_bf2(float x0, float x1,
                                          uint32_t& hi, uint32_t& lo)
{
    uint32_t h = pack_bf2(x0, x1);
    float h0 = __uint_as_float(h << 16);
    float h1 = __uint_as_float(h & 0xffff0000u);
    lo = pack_bf2(x0 - h0, x1 - h1);
    hi = h;
}
__device__ __forceinline__ void mma16(float* d,
                                      uint32_t a0, uint32_t a1, uint32_t a2, uint32_t a3,
                                      uint32_t b0, uint32_t b1)
{
    asm volatile(
        "mma.sync.aligned.m16n8k16.row.col.f32.bf16.bf16.f32 "
        "{%0,%1,%2,%3}, {%4,%5,%6,%7}, {%8,%9}, {%0,%1,%2,%3};\n"
        : "+f"(d[0]), "+f"(d[1]), "+f"(d[2]), "+f"(d[3])
        : "r"(a0), "r"(a1), "r"(a2), "r"(a3), "r"(b0), "r"(b1));
}
__device__ __forceinline__ void mma3(float* d,
                                     const uint32_t* ah, const uint32_t* al,
                                     uint32_t bh0, uint32_t bh1,
                                     uint32_t bl0, uint32_t bl1)
{
    mma16(d, ah[0], ah[1], ah[2], ah[3], bl0, bl1);
    mma16(d, al[0], al[1], al[2], al[3], bh0, bh1);
    mma16(d, ah[0], ah[1], ah[2], ah[3], bh0, bh1);
}
__device__ __forceinline__ uint32_t smem_u32(const void* p)
{
    uint32_t a;
    asm("{ .reg .u64 t; cvta.to.shared.u64 t, %1; cvt.u32.u64 %0, t; }"
        : "=r"(a) : "l"(p));
    return a;
}
__device__ __forceinline__ void cp16(uint32_t s, const void* g)
{
    asm volatile("cp.async.cg.shared.global [%0], [%1], 16;"
                 :: "r"(s), "l"(g) : "memory");
}
#define CP_COMMIT() asm volatile("cp.async.commit_group;" ::: "memory")
#define CP_WAIT1()  asm volatile("cp.async.wait_group 1;" ::: "memory")
#define CP_WAIT0()  asm volatile("cp.async.wait_group 0;" ::: "memory")

// ---------------------------------------------------------------------------
// Prep kernels (identical to R11)
// ---------------------------------------------------------------------------
__global__ __launch_bounds__(256) void x_prep(
    const float* __restrict__ Xq, const float* __restrict__ Xk,
    const float* __restrict__ Xv)
{
    const int z = blockIdx.z;
    const float* X = (z == 0) ? Xq : (z == 1) ? Xk : Xv;
    uint32_t* oh = g_xh[z];
    uint32_t* ol = g_xl[z];
    int i = blockIdx.x * 256 + threadIdx.x;
    float4 v = ((const float4*)X)[i];
    uint32_t h0, l0, h1, l1;
    split_bf2(v.x, v.y, h0, l0);
    split_bf2(v.z, v.w, h1, l1);
    uint2 uh; uh.x = h0; uh.y = h1;
    uint2 ul; ul.x = l0; ul.y = l1;
    *(uint2*)&oh[2 * i] = uh;
    *(uint2*)&ol[2 * i] = ul;
}

__global__ __launch_bounds__(256) void w_prep(
    const float* __restrict__ Wq, const float* __restrict__ Wk,
    const float* __restrict__ Wv, const float* __restrict__ Wo)
{
    const int z = blockIdx.z;
    const float* W = (z == 0) ? Wq : (z == 1) ? Wk : (z == 2) ? Wv : Wo;
    uint32_t* oh = g_wh[z];
    uint32_t* ol = g_wl[z];
    int idx = blockIdx.x * 256 + threadIdx.x;
    int kp = idx >> 8;
    int n4 = (idx & 255) * 4;
    float4 a = *(const float4*)(W + (size_t)(2 * kp) * DIMC + n4);
    float4 b = *(const float4*)(W + (size_t)(2 * kp + 1) * DIMC + n4);
    uint32_t hw[4], lw[4];
    split_bf2(a.x, b.x, hw[0], lw[0]);
    split_bf2(a.y, b.y, hw[1], lw[1]);
    split_bf2(a.z, b.z, hw[2], lw[2]);
    split_bf2(a.w, b.w, hw[3], lw[3]);
    *(uint4*)&oh[(size_t)kp * DIMC + n4] = *(uint4*)&hw[0];
    *(uint4*)&ol[(size_t)kp * DIMC + n4] = *(uint4*)&lw[0];
}

// ---------------------------------------------------------------------------
// GEMM: 128x128 block, BK=32 (16 kp), 256 threads, warp tile 64x32.
// cp.async double-buffered smem; fragment indexing identical to R11.
// Stage layout (words): sAh[128*20] sAl[128*20] sBh[16*136] sBl[16*136]
// ---------------------------------------------------------------------------
#define GAP 20
#define GBP 136
#define ST_AH 0
#define ST_AL 2560
#define ST_BH 5120
#define ST_BL 7296
#define ST_W  9472
#define GEMM_SMEM (2 * ST_W * 4)

__device__ __forceinline__ void gemm_load_chunk(
    uint32_t sb, int kb,
    const uint32_t* __restrict__ Ahg, const uint32_t* __restrict__ Alg,
    const uint32_t* __restrict__ Bhg, const uint32_t* __restrict__ Blg,
    int bm, int bn, int tid)
{
#pragma unroll
    for (int i = 0; i < 2; i++) {
        int fw = i * 1024 + tid * 4;
        int arow = fw >> 4, akp = fw & 15;
        size_t ga = (size_t)(bm + arow) * 512 + kb * 16 + akp;
        uint32_t so = sb + (arow * GAP + akp) * 4;
        cp16(so + ST_AH * 4, &Ahg[ga]);
        cp16(so + ST_AL * 4, &Alg[ga]);
        int bkp = fw >> 7, bnn = fw & 127;
        size_t gb = (size_t)(kb * 16 + bkp) * DIMC + bn + bnn;
        uint32_t sob = sb + (bkp * GBP + bnn) * 4;
        cp16(sob + ST_BH * 4, &Bhg[gb]);
        cp16(sob + ST_BL * 4, &Blg[gb]);
    }
    CP_COMMIT();
}

__device__ __forceinline__ void gemm_mainloop(
    const uint32_t* __restrict__ Ahg, const uint32_t* __restrict__ Alg,
    const uint32_t* __restrict__ Bhg, const uint32_t* __restrict__ Blg,
    int bm, int bn, uint32_t* smw, float acc[4][4][4])
{
    const int tid = threadIdx.x;
    const int lane = tid & 31;
    const int warp = tid >> 5;
    const int gid = lane >> 2;
    const int tg = lane & 3;
    const int wm = warp >> 2;   // 0..1
    const int wn = warp & 3;    // 0..3
    const uint32_t sb0 = smem_u32(smw);

    gemm_load_chunk(sb0, 0, Ahg, Alg, Bhg, Blg, bm, bn, tid);
    gemm_load_chunk(sb0 + ST_W * 4, 1, Ahg, Alg, Bhg, Blg, bm, bn, tid);

    for (int kb = 0; kb < 32; kb++) {
        if (kb < 31) { CP_WAIT1(); } else { CP_WAIT0(); }
        __syncthreads();

        const uint32_t* sAh = smw + (kb & 1) * ST_W + ST_AH;
        const uint32_t* sAl = smw + (kb & 1) * ST_W + ST_AL;
        const uint32_t* sBh = smw + (kb & 1) * ST_W + ST_BH;
        const uint32_t* sBl = smw + (kb & 1) * ST_W + ST_BL;

#pragma unroll
        for (int ks = 0; ks < 2; ks++) {
            const int kp0 = ks * 8;
            uint32_t ah[4][4], al[4][4];
#pragma unroll
            for (int mt = 0; mt < 4; mt++) {
                int r = wm * 64 + mt * 16 + gid;
                ah[mt][0] = sAh[r * GAP + kp0 + tg];
                ah[mt][1] = sAh[(r + 8) * GAP + kp0 + tg];
                ah[mt][2] = sAh[r * GAP + kp0 + 4 + tg];
                ah[mt][3] = sAh[(r + 8) * GAP + kp0 + 4 + tg];
                al[mt][0] = sAl[r * GAP + kp0 + tg];
                al[mt][1] = sAl[(r + 8) * GAP + kp0 + tg];
                al[mt][2] = sAl[r * GAP + kp0 + 4 + tg];
                al[mt][3] = sAl[(r + 8) * GAP + kp0 + 4 + tg];
            }
#pragma unroll
            for (int nt = 0; nt < 4; nt++) {
                int c = wn * 32 + nt * 8 + gid;
                uint32_t bh0 = sBh[(kp0 + tg) * GBP + c];
                uint32_t bh1 = sBh[(kp0 + 4 + tg) * GBP + c];
                uint32_t bl0 = sBl[(kp0 + tg) * GBP + c];
                uint32_t bl1 = sBl[(kp0 + 4 + tg) * GBP + c];
#pragma unroll
                for (int mt = 0; mt < 4; mt++)
                    mma3(acc[mt][nt], ah[mt], al[mt], bh0, bh1, bl0, bl1);
            }
        }
        __syncthreads();
        if (kb + 2 < 32)
            gemm_load_chunk(sb0 + (kb & 1) * ST_W * 4, kb + 2,
                            Ahg, Alg, Bhg, Blg, bm, bn, tid);
    }
}

// ---------------------------------------------------------------------------
// Fused QKV projection (z = 0/1/2 -> Q/K/V).
// ---------------------------------------------------------------------------
__global__ __launch_bounds__(256, 2) void mma_gemm_qkv()
{
    extern __shared__ __align__(16) uint32_t smw[];
    const int which = blockIdx.z;

    const int bm = blockIdx.x * 128;
    const int bn = blockIdx.y * 128;
    float acc[4][4][4];
#pragma unroll
    for (int mt = 0; mt < 4; mt++)
#pragma unroll
        for (int nt = 0; nt < 4; nt++)
#pragma unroll
            for (int c = 0; c < 4; c++) acc[mt][nt][c] = 0.f;

    gemm_mainloop(g_xh[which], g_xl[which], g_wh[which], g_wl[which],
                  bm, bn, smw, acc);

    const int lane = threadIdx.x & 31;
    const int warp = threadIdx.x >> 5;
    const int gid = lane >> 2, tg = lane & 3;
    const int wm = warp >> 2, wn = warp & 3;

    if (which < 2) {
        const float sc = (which == 0) ? 0.125f : 1.0f;
        uint32_t* Ch = (which == 0) ? g_qh : g_kh;
        uint32_t* Cl = (which == 0) ? g_ql : g_kl;
#pragma unroll
        for (int mt = 0; mt < 4; mt++) {
            int row = bm + wm * 64 + mt * 16 + gid;
#pragma unroll
            for (int nt = 0; nt < 4; nt++) {
                int col = bn + wn * 32 + nt * 8 + 2 * tg;
                int h = col >> 6, dp = (col & 63) >> 1;
#pragma unroll
                for (int half = 0; half < 2; half++) {
                    int r = row + half * 8;
                    int b = r >> 11, n = r & 2047;
                    uint32_t hw, lw;
                    split_bf2(acc[mt][nt][2 * half] * sc,
                              acc[mt][nt][2 * half + 1] * sc, hw, lw);
                    size_t wi = ((size_t)(b * HEADS + h) * NSEQ + n) * 32 + dp;
                    Ch[wi] = hw;
                    Cl[wi] = lw;
                }
            }
        }
    } else {
#pragma unroll
        for (int mt = 0; mt < 4; mt++) {
            int row = bm + wm * 64 + mt * 16 + gid;
#pragma unroll
            for (int nt = 0; nt < 4; nt++) {
                int col = bn + wn * 32 + nt * 8 + 2 * tg;
                int h = col >> 6, d = col & 63;
#pragma unroll
                for (int half = 0; half < 2; half++) {
                    int r = row + half * 8;
                    int b = r >> 11, n = r & 2047;
                    float2 v = make_float2(acc[mt][nt][2 * half],
                                           acc[mt][nt][2 * half + 1]);
                    *(float2*)&g_v[(((size_t)(b * HEADS + h) * NSEQ) + n) * DHEAD + d] = v;
                }
            }
        }
    }
}

// ---------------------------------------------------------------------------
// Wo projection
// ---------------------------------------------------------------------------
__global__ __launch_bounds__(256, 2) void mma_gemm_wo(const float* __restrict__ bo)
{
    extern __shared__ __align__(16) uint32_t smw[];

    const int bm = blockIdx.x * 128;
    const int bn = blockIdx.y * 128;
    float acc[4][4][4];
#pragma unroll
    for (int mt = 0; mt < 4; mt++)
#pragma unroll
        for (int nt = 0; nt < 4; nt++)
#pragma unroll
            for (int c = 0; c < 4; c++) acc[mt][nt][c] = 0.f;

    gemm_mainloop(g_ah, g_al, g_wh[3], g_wl[3], bm, bn, smw, acc);

    const int lane = threadIdx.x & 31;
    const int warp = threadIdx.x >> 5;
    const int gid = lane >> 2, tg = lane & 3;
    const int wm = warp >> 2, wn = warp & 3;

#pragma unroll
    for (int mt = 0; mt < 4; mt++) {
        int row = bm + wm * 64 + mt * 16 + gid;
#pragma unroll
        for (int nt = 0; nt < 4; nt++) {
            int col = bn + wn * 32 + nt * 8 + 2 * tg;
            float b0 = bo[col], b1 = bo[col + 1];
#pragma unroll
            for (int half = 0; half < 2; half++) {
                int r = row + half * 8;
                float2 v = make_float2(acc[mt][nt][2 * half] + b0,
                                       acc[mt][nt][2 * half + 1] + b1);
                *(float2*)&g_proj[(size_t)r * DIMC + col] = v;
            }
        }
    }
}

// ---------------------------------------------------------------------------
// Flash attention (identical to R11). Grid: (N/128, B*H), 256 threads.
// ---------------------------------------------------------------------------
#define AQP 36
#define AKP 36
#define AVP 72
#define QW  (128 * AQP)
#define KW  (64 * AKP)
#define VW  (32 * AVP)
#define ATTN_SMEM ((2 * (QW + KW + VW)) * 4)

__global__ __launch_bounds__(256, 2) void attn_mma()
{
    extern __shared__ __align__(16) uint32_t smw[];
    uint32_t* sQh = smw;
    uint32_t* sQl = sQh + QW;
    uint32_t* sKh = sQl + QW;
    uint32_t* sKl = sKh + KW;
    uint32_t* sVh = sKl + KW;
    uint32_t* sVl = sVh + VW;

    const int tid = threadIdx.x;
    const int w = tid >> 5;
    const int lane = tid & 31;
    const int gid = lane >> 2, tg = lane & 3;
    const int qt = blockIdx.x;
    const int bh = blockIdx.y;

    const size_t rowbase = (size_t)bh * NSEQ * 32;
    const float* Vg = g_v + (size_t)bh * NSEQ * DHEAD;

    {
        const size_t qbase = rowbase + (size_t)qt * 128 * 32;
#pragma unroll
        for (int i = 0; i < 4; i++) {
            int fw = i * 1024 + tid * 4;
            int row = fw >> 5, kpo = fw & 31;
            uint4 h = *(const uint4*)&g_qh[qbase + fw];
            uint4 l = *(const uint4*)&g_ql[qbase + fw];
            *(uint4*)&sQh[row * AQP + kpo] = h;
            *(uint4*)&sQl[row * AQP + kpo] = l;
        }
    }
    __syncthreads();

    uint32_t qh[4][4], ql[4][4];
#pragma unroll
    for (int ks = 0; ks < 4; ks++) {
        const int kp0 = ks * 8;
        const int r = w * 16 + gid;
        qh[ks][0] = sQh[r * AQP + kp0 + tg];
        qh[ks][1] = sQh[(r + 8) * AQP + kp0 + tg];
        qh[ks][2] = sQh[r * AQP + kp0 + 4 + tg];
        qh[ks][3] = sQh[(r + 8) * AQP + kp0 + 4 + tg];
        ql[ks][0] = sQl[r * AQP + kp0 + tg];
        ql[ks][1] = sQl[(r + 8) * AQP + kp0 + tg];
        ql[ks][2] = sQl[r * AQP + kp0 + 4 + tg];
        ql[ks][3] = sQl[(r + 8) * AQP + kp0 + 4 + tg];
    }

    float m_[2], l_[2], o[8][4];
#pragma unroll
    for (int h = 0; h < 2; h++) { m_[h] = -1e30f; l_[h] = 0.f; }
#pragma unroll
    for (int nt = 0; nt < 8; nt++)
#pragma unroll
        for (int c = 0; c < 4; c++) o[nt][c] = 0.f;

    for (int kt = 0; kt < NSEQ / 64; kt++) {
        __syncthreads();
        {
            const size_t kb = rowbase + (size_t)kt * 64 * 32;
#pragma unroll
            for (int i = 0; i < 2; i++) {
                int fw = i * 1024 + tid * 4;
                int kv = fw >> 5, kpo = fw & 31;
                uint4 h = *(const uint4*)&g_kh[kb + fw];
                uint4 l = *(const uint4*)&g_kl[kb + fw];
                *(uint4*)&sKh[kv * AKP + kpo] = h;
                *(uint4*)&sKl[kv * AKP + kpo] = l;
            }
        }
#pragma unroll
        for (int i = 0; i < 2; i++) {
            int task = i * 256 + tid;
            int kvp = task >> 4, d0 = (task & 15) * 4;
            float4 v0 = *(const float4*)(Vg + (kt * 64 + 2 * kvp) * DHEAD + d0);
            float4 v1 = *(const float4*)(Vg + (kt * 64 + 2 * kvp + 1) * DHEAD + d0);
            uint32_t hh[4], ll[4];
            split_bf2(v0.x, v1.x, hh[0], ll[0]);
            split_bf2(v0.y, v1.y, hh[1], ll[1]);
            split_bf2(v0.z, v1.z, hh[2], ll[2]);
            split_bf2(v0.w, v1.w, hh[3], ll[3]);
            *(uint4*)&sVh[kvp * AVP + d0] = *(uint4*)&hh[0];
            *(uint4*)&sVl[kvp * AVP + d0] = *(uint4*)&ll[0];
        }
        __syncthreads();

        float s[8][4];
#pragma unroll
        for (int nt = 0; nt < 8; nt++)
#pragma unroll
            for (int c = 0; c < 4; c++) s[nt][c] = 0.f;

#pragma unroll
        for (int ks = 0; ks < 4; ks++) {
            const int kp0 = ks * 8;
#pragma unroll
            for (int nt = 0; nt < 8; nt++) {
                int c = nt * 8 + gid;
                uint32_t bh0 = sKh[c * AKP + kp0 + tg];
                uint32_t bh1 = sKh[c * AKP + kp0 + 4 + tg];
                uint32_t bl0 = sKl[c * AKP + kp0 + tg];
                uint32_t bl1 = sKl[c * AKP + kp0 + 4 + tg];
                mma3(s[nt], qh[ks], ql[ks], bh0, bh1, bl0, bl1);
            }
        }

#pragma unroll
        for (int h = 0; h < 2; h++) {
            float mx = -1e30f;
#pragma unroll
            for (int nt = 0; nt < 8; nt++)
                mx = fmaxf(mx, fmaxf(s[nt][2 * h], s[nt][2 * h + 1]));
            mx = fmaxf(mx, __shfl_xor_sync(0xffffffffu, mx, 1));
            mx = fmaxf(mx, __shfl_xor_sync(0xffffffffu, mx, 2));
            float mnew = fmaxf(m_[h], mx);
            float corr = __expf(m_[h] - mnew);
            m_[h] = mnew;
            float rs = 0.f;
#pragma unroll
            for (int nt = 0; nt < 8; nt++) {
                float p0 = __expf(s[nt][2 * h] - mnew);
                float p1 = __expf(s[nt][2 * h + 1] - mnew);
                s[nt][2 * h] = p0;
                s[nt][2 * h + 1] = p1;
                rs += p0 + p1;
            }
            rs += __shfl_xor_sync(0xffffffffu, rs, 1);
            rs += __shfl_xor_sync(0xffffffffu, rs, 2);
            l_[h] = l_[h] * corr + rs;
#pragma unroll
            for (int nt = 0; nt < 8; nt++) {
                o[nt][2 * h] *= corr;
                o[nt][2 * h + 1] *= corr;
            }
        }

#pragma unroll
        for (int ks = 0; ks < 4; ks++) {
            uint32_t pah[4], pal[4];
            split_bf2(s[2 * ks][0],     s[2 * ks][1],     pah[0], pal[0]);
            split_bf2(s[2 * ks][2],     s[2 * ks][3],     pah[1], pal[1]);
            split_bf2(s[2 * ks + 1][0], s[2 * ks + 1][1], pah[2], pal[2]);
            split_bf2(s[2 * ks + 1][2], s[2 * ks + 1][3], pah[3], pal[3]);
            const int kp0 = ks * 8;
#pragma unroll
            for (int nt = 0; nt < 8; nt++) {
                int d = nt * 8 + gid;
                uint32_t bh0 = sVh[(kp0 + tg) * AVP + d];
                uint32_t bh1 = sVh[(kp0 + 4 + tg) * AVP + d];
                uint32_t bl0 = sVl[(kp0 + tg) * AVP + d];
                uint32_t bl1 = sVl[(kp0 + 4 + tg) * AVP + d];
                mma3(o[nt], pah, pal, bh0, bh1, bl0, bl1);
            }
        }
    }

    const int b = bh >> 4;
    const int hh = bh & 15;
#pragma unroll
    for (int h = 0; h < 2; h++) {
        float inv = 1.0f / l_[h];
        int n = qt * 128 + w * 16 + gid + h * 8;
        size_t rw = (size_t)(b * NSEQ + n) * 512;
#pragma unroll
        for (int nt = 0; nt < 8; nt++) {
            int cp = hh * 32 + nt * 4 + tg;
            uint32_t hw, lw;
            split_bf2(o[nt][2 * h] * inv, o[nt][2 * h + 1] * inv, hw, lw);
            g_ah[rw + cp] = hw;
            g_al[rw + cp] = lw;
        }
    }
}

// ---------------------------------------------------------------------------
// LayerNorm over last dim + residual.
// ---------------------------------------------------------------------------
__global__ __launch_bounds__(256) void ln_kernel(
    const float* __restrict__ query, const float* __restrict__ gamma,
    const float* __restrict__ beta, float* __restrict__ out)
{
    const int r = blockIdx.x;
    const float* x = g_proj + (size_t)r * DIMC;

    float v[4];
    float s = 0.f, ss = 0.f;
#pragma unroll
    for (int i = 0; i < 4; i++) {
        v[i] = x[threadIdx.x + 256 * i];
        s += v[i];
        ss += v[i] * v[i];
    }
#pragma unroll
    for (int ofs = 16; ofs > 0; ofs >>= 1) {
        s  += __shfl_xor_sync(0xffffffffu, s,  ofs);
        ss += __shfl_xor_sync(0xffffffffu, ss, ofs);
    }
    __shared__ float rs[8], rss[8];
    int w = threadIdx.x >> 5, lane = threadIdx.x & 31;
    if (lane == 0) { rs[w] = s; rss[w] = ss; }
    __syncthreads();
    if (threadIdx.x == 0) {
        float a = 0.f, b2 = 0.f;
#pragma unroll
        for (int i = 0; i < 8; i++) { a += rs[i]; b2 += rss[i]; }
        rs[0] = a; rss[0] = b2;
    }
    __syncthreads();
    const float mean = rs[0] * (1.0f / DIMC);
    const float var  = rss[0] * (1.0f / DIMC) - mean * mean;
    const float inv  = rsqrtf(var + 1e-5f);

#pragma unroll
    for (int i = 0; i < 4; i++) {
        int c = threadIdx.x + 256 * i;
        size_t idx = (size_t)r * DIMC + c;
        out[idx] = (v[i] - mean) * inv * gamma[c] + beta[c] + query[idx];
    }
}

// ---------------------------------------------------------------------------
extern "C" void kernel_launch(void* const* d_in, const int* in_sizes, int n_in,
                              void* d_out, int out_size)
{
    const float* query = (const float*)d_in[0];
    const float* key_  = (const float*)d_in[1];
    const float* value = (const float*)d_in[2];
    const float* Wq    = (const float*)d_in[3];
    const float* Wk    = (const float*)d_in[4];
    const float* Wv    = (const float*)d_in[5];
    const float* Wo    = (const float*)d_in[6];
    const float* bo    = (const float*)d_in[7];
    const float* gamma = (const float*)d_in[8];
    const float* beta  = (const float*)d_in[9];
    float* out = (float*)d_out;

    cudaFuncSetAttribute(attn_mma,
                         cudaFuncAttributeMaxDynamicSharedMemorySize, ATTN_SMEM);
    cudaFuncSetAttribute(mma_gemm_qkv,
                         cudaFuncAttributeMaxDynamicSharedMemorySize, GEMM_SMEM);
    cudaFuncSetAttribute(mma_gemm_wo,
                         cudaFuncAttributeMaxDynamicSharedMemorySize, GEMM_SMEM);

    // 0) split prep
    x_prep<<<dim3(MTOT * DIMC / 1024, 1, 3), 256>>>(query, key_, value);
    w_prep<<<dim3(WWRD / 1024, 1, 4), 256>>>(Wq, Wk, Wv, Wo);

    // 1) QKV projections (fused, cp.async double-buffered)
    mma_gemm_qkv<<<dim3(MTOT / 128, DIMC / 128, 3), 256, GEMM_SMEM>>>();
    // 2) Attention
    attn_mma<<<dim3(NSEQ / 128, BC * HEADS), 256, ATTN_SMEM>>>();
    // 3) Wo projection + bias
    mma_gemm_wo<<<dim3(MTOT / 128, DIMC / 128), 256, GEMM_SMEM>>>(bo);
    // 4) LayerNorm + residual
    ln_kernel<<<MTOT, 256>>>(query, gamma, beta, out);
}

// round 17
// speedup vs baseline: 2.0184x; 1.0131x over previous
#include <cuda_runtime.h>
#include <cstdint>

// ---------------------------------------------------------------------------
// MultiHeadAttention: out = LN( softmax(QK^T/sqrt(d)) V @ Wo + bo ) + query
// B=4, N=2048, DIM=1024, HEADS=16, DH=64
// Round-16: R14 winner + attention loaders -> pure cp.async copies with
// double-buffered K/V stages (stage1 overlays dead sQ region); V pre-packed.
// ---------------------------------------------------------------------------

#define BC    4
#define NSEQ  2048
#define DIMC  1024
#define HEADS 16
#define DHEAD 64
#define MTOT  (BC * NSEQ)          // 8192
#define XWRD  (MTOT * (DIMC / 2))
#define WWRD  ((DIMC / 2) * DIMC)
#define VPW   (BC * HEADS * (NSEQ / 2) * DHEAD)   // packed V words

__device__ uint32_t g_xh[3][XWRD], g_xl[3][XWRD];   // X inputs, [m][kp]
__device__ uint32_t g_wh[4][WWRD], g_wl[4][WWRD];   // W, [kp][n]
__device__ uint32_t g_qh[XWRD], g_ql[XWRD];         // Q packed, scaled 1/8
__device__ uint32_t g_kh[XWRD], g_kl[XWRD];         // K packed
__device__ float    g_v[MTOT * DIMC];               // V fp32 [B,H,N,DH]
__device__ uint32_t g_vph[VPW], g_vpl[VPW];         // V packed pairs along seq
__device__ uint32_t g_ah[XWRD], g_al[XWRD];         // attn out packed
__device__ float    g_proj[MTOT * DIMC];

// ---------------------------------------------------------------------------
__device__ __forceinline__ uint32_t pack_bf2(float x0, float x1)
{
    uint32_t p;
    asm("cvt.rn.satfinite.bf16x2.f32 %0, %1, %2;" : "=r"(p) : "f"(x1), "f"(x0));
    return p;
}
__device__ __forceinline__ void split_bf2(float x0, float x1,
                                          uint32_t& hi, uint32_t& lo)
{
    uint32_t h = pack_bf2(x0, x1);
    float h0 = __uint_as_float(h << 16);
    float h1 = __uint_as_float(h & 0xffff0000u);
    lo = pack_bf2(x0 - h0, x1 - h1);
    hi = h;
}
__device__ __forceinline__ void mma16(float* d,
                                      uint32_t a0, uint32_t a1, uint32_t a2, uint32_t a3,
                                      uint32_t b0, uint32_t b1)
{
    asm volatile(
        "mma.sync.aligned.m16n8k16.row.col.f32.bf16.bf16.f32 "
        "{%0,%1,%2,%3}, {%4,%5,%6,%7}, {%8,%9}, {%0,%1,%2,%3};\n"
        : "+f"(d[0]), "+f"(d[1]), "+f"(d[2]), "+f"(d[3])
        : "r"(a0), "r"(a1), "r"(a2), "r"(a3), "r"(b0), "r"(b1));
}
__device__ __forceinline__ void mma3(float* d,
                                     const uint32_t* ah, const uint32_t* al,
                                     uint32_t bh0, uint32_t bh1,
                                     uint32_t bl0, uint32_t bl1)
{
    mma16(d, ah[0], ah[1], ah[2], ah[3], bl0, bl1);
    mma16(d, al[0], al[1], al[2], al[3], bh0, bh1);
    mma16(d, ah[0], ah[1], ah[2], ah[3], bh0, bh1);
}
__device__ __forceinline__ uint32_t smem_u32(const void* p)
{
    uint32_t a;
    asm("{ .reg .u64 t; cvta.to.shared.u64 t, %1; cvt.u32.u64 %0, t; }"
        : "=r"(a) : "l"(p));
    return a;
}
__device__ __forceinline__ void cp16(uint32_t s, const void* g)
{
    asm volatile("cp.async.cg.shared.global [%0], [%1], 16;"
                 :: "r"(s), "l"(g) : "memory");
}
#define CP_COMMIT() asm volatile("cp.async.commit_group;" ::: "memory")
#define CP_WAIT1()  asm volatile("cp.async.wait_group 1;" ::: "memory")
#define CP_WAIT0()  asm volatile("cp.async.wait_group 0;" ::: "memory")

// ---------------------------------------------------------------------------
// Prep kernels
// ---------------------------------------------------------------------------
__global__ __launch_bounds__(256) void x_prep(
    const float* __restrict__ Xq, const float* __restrict__ Xk,
    const float* __restrict__ Xv)
{
    const int z = blockIdx.z;
    const float* X = (z == 0) ? Xq : (z == 1) ? Xk : Xv;
    uint32_t* oh = g_xh[z];
    uint32_t* ol = g_xl[z];
    int i = blockIdx.x * 256 + threadIdx.x;
    float4 v = ((const float4*)X)[i];
    uint32_t h0, l0, h1, l1;
    split_bf2(v.x, v.y, h0, l0);
    split_bf2(v.z, v.w, h1, l1);
    uint2 uh; uh.x = h0; uh.y = h1;
    uint2 ul; ul.x = l0; ul.y = l1;
    *(uint2*)&oh[2 * i] = uh;
    *(uint2*)&ol[2 * i] = ul;
}

__global__ __launch_bounds__(256) void w_prep(
    const float* __restrict__ Wq, const float* __restrict__ Wk,
    const float* __restrict__ Wv, const float* __restrict__ Wo)
{
    const int z = blockIdx.z;
    const float* W = (z == 0) ? Wq : (z == 1) ? Wk : (z == 2) ? Wv : Wo;
    uint32_t* oh = g_wh[z];
    uint32_t* ol = g_wl[z];
    int idx = blockIdx.x * 256 + threadIdx.x;
    int kp = idx >> 8;
    int n4 = (idx & 255) * 4;
    float4 a = *(const float4*)(W + (size_t)(2 * kp) * DIMC + n4);
    float4 b = *(const float4*)(W + (size_t)(2 * kp + 1) * DIMC + n4);
    uint32_t hw[4], lw[4];
    split_bf2(a.x, b.x, hw[0], lw[0]);
    split_bf2(a.y, b.y, hw[1], lw[1]);
    split_bf2(a.z, b.z, hw[2], lw[2]);
    split_bf2(a.w, b.w, hw[3], lw[3]);
    *(uint4*)&oh[(size_t)kp * DIMC + n4] = *(uint4*)&hw[0];
    *(uint4*)&ol[(size_t)kp * DIMC + n4] = *(uint4*)&lw[0];
}

// V pack: fp32 [B,H,N,DH] -> bf16 hi/lo pairs along seq, [bh*1024+kvp][64]
__global__ __launch_bounds__(256) void v_pack()
{
    int t = blockIdx.x * 256 + threadIdx.x;   // 1,048,576 tasks
    int dq = (t & 15) * 4;
    size_t kvpg = (size_t)(t >> 4);
    const float* r0 = g_v + kvpg * 2 * DHEAD + dq;
    float4 v0 = *(const float4*)r0;
    float4 v1 = *(const float4*)(r0 + DHEAD);
    uint32_t hh[4], ll[4];
    split_bf2(v0.x, v1.x, hh[0], ll[0]);
    split_bf2(v0.y, v1.y, hh[1], ll[1]);
    split_bf2(v0.z, v1.z, hh[2], ll[2]);
    split_bf2(v0.w, v1.w, hh[3], ll[3]);
    *(uint4*)&g_vph[kvpg * DHEAD + dq] = *(uint4*)&hh[0];
    *(uint4*)&g_vpl[kvpg * DHEAD + dq] = *(uint4*)&ll[0];
}

// ---------------------------------------------------------------------------
// GEMM (identical to R14/R16 winner): cp.async double-buffered, 2 CTAs/SM.
// ---------------------------------------------------------------------------
#define GAP 20
#define GBP 136
#define ST_AH 0
#define ST_AL 2560
#define ST_BH 5120
#define ST_BL 7296
#define ST_W  9472
#define GEMM_SMEM (2 * ST_W * 4)

__device__ __forceinline__ void gemm_load_chunk(
    uint32_t sb, int kb,
    const uint32_t* __restrict__ Ahg, const uint32_t* __restrict__ Alg,
    const uint32_t* __restrict__ Bhg, const uint32_t* __restrict__ Blg,
    int bm, int bn, int tid)
{
#pragma unroll
    for (int i = 0; i < 2; i++) {
        int fw = i * 1024 + tid * 4;
        int arow = fw >> 4, akp = fw & 15;
        size_t ga = (size_t)(bm + arow) * 512 + kb * 16 + akp;
        uint32_t so = sb + (arow * GAP + akp) * 4;
        cp16(so + ST_AH * 4, &Ahg[ga]);
        cp16(so + ST_AL * 4, &Alg[ga]);
        int bkp = fw >> 7, bnn = fw & 127;
        size_t gb = (size_t)(kb * 16 + bkp) * DIMC + bn + bnn;
        uint32_t sob = sb + (bkp * GBP + bnn) * 4;
        cp16(sob + ST_BH * 4, &Bhg[gb]);
        cp16(sob + ST_BL * 4, &Blg[gb]);
    }
    CP_COMMIT();
}

__device__ __forceinline__ void gemm_mainloop(
    const uint32_t* __restrict__ Ahg, const uint32_t* __restrict__ Alg,
    const uint32_t* __restrict__ Bhg, const uint32_t* __restrict__ Blg,
    int bm, int bn, uint32_t* smw, float acc[4][4][4])
{
    const int tid = threadIdx.x;
    const int lane = tid & 31;
    const int warp = tid >> 5;
    const int gid = lane >> 2;
    const int tg = lane & 3;
    const int wm = warp >> 2;
    const int wn = warp & 3;
    const uint32_t sb0 = smem_u32(smw);

    gemm_load_chunk(sb0, 0, Ahg, Alg, Bhg, Blg, bm, bn, tid);
    gemm_load_chunk(sb0 + ST_W * 4, 1, Ahg, Alg, Bhg, Blg, bm, bn, tid);

    for (int kb = 0; kb < 32; kb++) {
        if (kb < 31) { CP_WAIT1(); } else { CP_WAIT0(); }
        __syncthreads();

        const uint32_t* sAh = smw + (kb & 1) * ST_W + ST_AH;
        const uint32_t* sAl = smw + (kb & 1) * ST_W + ST_AL;
        const uint32_t* sBh = smw + (kb & 1) * ST_W + ST_BH;
        const uint32_t* sBl = smw + (kb & 1) * ST_W + ST_BL;

#pragma unroll
        for (int ks = 0; ks < 2; ks++) {
            const int kp0 = ks * 8;
            uint32_t ah[4][4], al[4][4];
#pragma unroll
            for (int mt = 0; mt < 4; mt++) {
                int r = wm * 64 + mt * 16 + gid;
                ah[mt][0] = sAh[r * GAP + kp0 + tg];
                ah[mt][1] = sAh[(r + 8) * GAP + kp0 + tg];
                ah[mt][2] = sAh[r * GAP + kp0 + 4 + tg];
                ah[mt][3] = sAh[(r + 8) * GAP + kp0 + 4 + tg];
                al[mt][0] = sAl[r * GAP + kp0 + tg];
                al[mt][1] = sAl[(r + 8) * GAP + kp0 + tg];
                al[mt][2] = sAl[r * GAP + kp0 + 4 + tg];
                al[mt][3] = sAl[(r + 8) * GAP + kp0 + 4 + tg];
            }
#pragma unroll
            for (int nt = 0; nt < 4; nt++) {
                int c = wn * 32 + nt * 8 + gid;
                uint32_t bh0 = sBh[(kp0 + tg) * GBP + c];
                uint32_t bh1 = sBh[(kp0 + 4 + tg) * GBP + c];
                uint32_t bl0 = sBl[(kp0 + tg) * GBP + c];
                uint32_t bl1 = sBl[(kp0 + 4 + tg) * GBP + c];
#pragma unroll
                for (int mt = 0; mt < 4; mt++)
                    mma3(acc[mt][nt], ah[mt], al[mt], bh0, bh1, bl0, bl1);
            }
        }
        __syncthreads();
        if (kb + 2 < 32)
            gemm_load_chunk(sb0 + (kb & 1) * ST_W * 4, kb + 2,
                            Ahg, Alg, Bhg, Blg, bm, bn, tid);
    }
}

__global__ __launch_bounds__(256, 2) void mma_gemm_qkv()
{
    extern __shared__ __align__(16) uint32_t smw[];
    const int which = blockIdx.z;

    const int bm = blockIdx.x * 128;
    const int bn = blockIdx.y * 128;
    float acc[4][4][4];
#pragma unroll
    for (int mt = 0; mt < 4; mt++)
#pragma unroll
        for (int nt = 0; nt < 4; nt++)
#pragma unroll
            for (int c = 0; c < 4; c++) acc[mt][nt][c] = 0.f;

    gemm_mainloop(g_xh[which], g_xl[which], g_wh[which], g_wl[which],
                  bm, bn, smw, acc);

    const int lane = threadIdx.x & 31;
    const int warp = threadIdx.x >> 5;
    const int gid = lane >> 2, tg = lane & 3;
    const int wm = warp >> 2, wn = warp & 3;

    if (which < 2) {
        const float sc = (which == 0) ? 0.125f : 1.0f;
        uint32_t* Ch = (which == 0) ? g_qh : g_kh;
        uint32_t* Cl = (which == 0) ? g_ql : g_kl;
#pragma unroll
        for (int mt = 0; mt < 4; mt++) {
            int row = bm + wm * 64 + mt * 16 + gid;
#pragma unroll
            for (int nt = 0; nt < 4; nt++) {
                int col = bn + wn * 32 + nt * 8 + 2 * tg;
                int h = col >> 6, dp = (col & 63) >> 1;
#pragma unroll
                for (int half = 0; half < 2; half++) {
                    int r = row + half * 8;
                    int b = r >> 11, n = r & 2047;
                    uint32_t hw, lw;
                    split_bf2(acc[mt][nt][2 * half] * sc,
                              acc[mt][nt][2 * half + 1] * sc, hw, lw);
                    size_t wi = ((size_t)(b * HEADS + h) * NSEQ + n) * 32 + dp;
                    Ch[wi] = hw;
                    Cl[wi] = lw;
                }
            }
        }
    } else {
#pragma unroll
        for (int mt = 0; mt < 4; mt++) {
            int row = bm + wm * 64 + mt * 16 + gid;
#pragma unroll
            for (int nt = 0; nt < 4; nt++) {
                int col = bn + wn * 32 + nt * 8 + 2 * tg;
                int h = col >> 6, d = col & 63;
#pragma unroll
                for (int half = 0; half < 2; half++) {
                    int r = row + half * 8;
                    int b = r >> 11, n = r & 2047;
                    float2 v = make_float2(acc[mt][nt][2 * half],
                                           acc[mt][nt][2 * half + 1]);
                    *(float2*)&g_v[(((size_t)(b * HEADS + h) * NSEQ) + n) * DHEAD + d] = v;
                }
            }
        }
    }
}

__global__ __launch_bounds__(256, 2) void mma_gemm_wo(const float* __restrict__ bo)
{
    extern __shared__ __align__(16) uint32_t smw[];

    const int bm = blockIdx.x * 128;
    const int bn = blockIdx.y * 128;
    float acc[4][4][4];
#pragma unroll
    for (int mt = 0; mt < 4; mt++)
#pragma unroll
        for (int nt = 0; nt < 4; nt++)
#pragma unroll
            for (int c = 0; c < 4; c++) acc[mt][nt][c] = 0.f;

    gemm_mainloop(g_ah, g_al, g_wh[3], g_wl[3], bm, bn, smw, acc);

    const int lane = threadIdx.x & 31;
    const int warp = threadIdx.x >> 5;
    const int gid = lane >> 2, tg = lane & 3;
    const int wm = warp >> 2, wn = warp & 3;

#pragma unroll
    for (int mt = 0; mt < 4; mt++) {
        int row = bm + wm * 64 + mt * 16 + gid;
#pragma unroll
        for (int nt = 0; nt < 4; nt++) {
            int col = bn + wn * 32 + nt * 8 + 2 * tg;
            float b0 = bo[col], b1 = bo[col + 1];
#pragma unroll
            for (int half = 0; half < 2; half++) {
                int r = row + half * 8;
                float2 v = make_float2(acc[mt][nt][2 * half] + b0,
                                       acc[mt][nt][2 * half + 1] + b1);
                *(float2*)&g_proj[(size_t)r * DIMC + col] = v;
            }
        }
    }
}

// ---------------------------------------------------------------------------
// Flash attention: cp.async double-buffered K/V (stage1 overlays dead sQ).
// smem layout (words): stage0 [0,9216): Kh 0, Kl 2304, Vh 4608, Vl 6912
//                      stage1/Q [9216,18432): overlays sQh(9216)/sQl(13824)
// ---------------------------------------------------------------------------
#define AQP 36
#define AKP 36
#define AVP 72
#define STW 9216
#define KHO 0
#define KLO 2304
#define VHO 4608
#define VLO 6912
#define QHO 9216
#define QLO 13824
#define ATTN_SMEM (2 * STW * 4)

__device__ __forceinline__ void attn_load(uint32_t sb, int kt, int stage,
                                          size_t krow, size_t vbase, int tid)
{
    const uint32_t st = sb + stage * (STW * 4);
    const size_t kb = krow + (size_t)kt * 64 * 32;
    const size_t vb = vbase + (size_t)kt * 32 * DHEAD;
#pragma unroll
    for (int i = 0; i < 2; i++) {
        int c = i * 256 + tid;
        int kv = c >> 3, wq = (c & 7) * 4;
        uint32_t dk = st + (KHO + kv * AKP + wq) * 4;
        cp16(dk, &g_kh[kb + kv * 32 + wq]);
        cp16(dk + (KLO - KHO) * 4, &g_kl[kb + kv * 32 + wq]);
        int kvp = c >> 4, dq = (c & 15) * 4;
        uint32_t dv = st + (VHO + kvp * AVP + dq) * 4;
        cp16(dv, &g_vph[vb + kvp * DHEAD + dq]);
        cp16(dv + (VLO - VHO) * 4, &g_vpl[vb + kvp * DHEAD + dq]);
    }
    CP_COMMIT();
}

__global__ __launch_bounds__(256, 2) void attn_mma()
{
    extern __shared__ __align__(16) uint32_t smw[];
    const int tid = threadIdx.x;
    const int w = tid >> 5;
    const int lane = tid & 31;
    const int gid = lane >> 2, tg = lane & 3;
    const int qt = blockIdx.x;
    const int bh = blockIdx.y;

    const size_t krow = (size_t)bh * NSEQ * 32;
    const size_t vbase = (size_t)bh * (NSEQ / 2) * DHEAD;
    const uint32_t sb = smem_u32(smw);

    // ---- load Q tile into the stage1 region (plain copies) ----
    {
        const size_t qbase = krow + (size_t)qt * 128 * 32;
        uint32_t* sQh = smw + QHO;
        uint32_t* sQl = smw + QLO;
#pragma unroll
        for (int i = 0; i < 4; i++) {
            int fw = i * 1024 + tid * 4;
            int row = fw >> 5, kpo = fw & 31;
            uint4 h = *(const uint4*)&g_qh[qbase + fw];
            uint4 l = *(const uint4*)&g_ql[qbase + fw];
            *(uint4*)&sQh[row * AQP + kpo] = h;
            *(uint4*)&sQl[row * AQP + kpo] = l;
        }
    }
    __syncthreads();

    // ---- hoist Q fragments, then Q smem becomes stage1 ----
    uint32_t qh[4][4], ql[4][4];
    {
        const uint32_t* sQh = smw + QHO;
        const uint32_t* sQl = smw + QLO;
#pragma unroll
        for (int ks = 0; ks < 4; ks++) {
            const int kp0 = ks * 8;
            const int r = w * 16 + gid;
            qh[ks][0] = sQh[r * AQP + kp0 + tg];
            qh[ks][1] = sQh[(r + 8) * AQP + kp0 + tg];
            qh[ks][2] = sQh[r * AQP + kp0 + 4 + tg];
            qh[ks][3] = sQh[(r + 8) * AQP + kp0 + 4 + tg];
            ql[ks][0] = sQl[r * AQP + kp0 + tg];
            ql[ks][1] = sQl[(r + 8) * AQP + kp0 + tg];
            ql[ks][2] = sQl[r * AQP + kp0 + 4 + tg];
            ql[ks][3] = sQl[(r + 8) * AQP + kp0 + 4 + tg];
        }
    }
    __syncthreads();   // all warps done reading sQ

    float m_[2], l_[2], o[8][4];
#pragma unroll
    for (int h = 0; h < 2; h++) { m_[h] = -1e30f; l_[h] = 0.f; }
#pragma unroll
    for (int nt = 0; nt < 8; nt++)
#pragma unroll
        for (int c = 0; c < 4; c++) o[nt][c] = 0.f;

    attn_load(sb, 0, 0, krow, vbase, tid);   // prologue: stage0 <- kt 0

    for (int kt = 0; kt < NSEQ / 64; kt++) {
        if (kt + 1 < NSEQ / 64) {
            attn_load(sb, kt + 1, (kt + 1) & 1, krow, vbase, tid);
            CP_WAIT1();
        } else {
            CP_WAIT0();
        }
        __syncthreads();

        const uint32_t* st = smw + (kt & 1) * STW;
        const uint32_t* sKh = st + KHO;
        const uint32_t* sKl = st + KLO;
        const uint32_t* sVh = st + VHO;
        const uint32_t* sVl = st + VLO;

        // ---- S = Q @ K^T ----
        float s[8][4];
#pragma unroll
        for (int nt = 0; nt < 8; nt++)
#pragma unroll
            for (int c = 0; c < 4; c++) s[nt][c] = 0.f;

#pragma unroll
        for (int ks = 0; ks < 4; ks++) {
            const int kp0 = ks * 8;
#pragma unroll
            for (int nt = 0; nt < 8; nt++) {
                int c = nt * 8 + gid;
                uint32_t bh0 = sKh[c * AKP + kp0 + tg];
                uint32_t bh1 = sKh[c * AKP + kp0 + 4 + tg];
                uint32_t bl0 = sKl[c * AKP + kp0 + tg];
                uint32_t bl1 = sKl[c * AKP + kp0 + 4 + tg];
                mma3(s[nt], qh[ks], ql[ks], bh0, bh1, bl0, bl1);
            }
        }

        // ---- online softmax ----
#pragma unroll
        for (int h = 0; h < 2; h++) {
            float mx = -1e30f;
#pragma unroll
            for (int nt = 0; nt < 8; nt++)
                mx = fmaxf(mx, fmaxf(s[nt][2 * h], s[nt][2 * h + 1]));
            mx = fmaxf(mx, __shfl_xor_sync(0xffffffffu, mx, 1));
            mx = fmaxf(mx, __shfl_xor_sync(0xffffffffu, mx, 2));
            float mnew = fmaxf(m_[h], mx);
            float corr = __expf(m_[h] - mnew);
            m_[h] = mnew;
            float rs = 0.f;
#pragma unroll
            for (int nt = 0; nt < 8; nt++) {
                float p0 = __expf(s[nt][2 * h] - mnew);
                float p1 = __expf(s[nt][2 * h + 1] - mnew);
                s[nt][2 * h] = p0;
                s[nt][2 * h + 1] = p1;
                rs += p0 + p1;
            }
            rs += __shfl_xor_sync(0xffffffffu, rs, 1);
            rs += __shfl_xor_sync(0xffffffffu, rs, 2);
            l_[h] = l_[h] * corr + rs;
#pragma unroll
            for (int nt = 0; nt < 8; nt++) {
                o[nt][2 * h] *= corr;
                o[nt][2 * h + 1] *= corr;
            }
        }

        // ---- O += P @ V ----
#pragma unroll
        for (int ks = 0; ks < 4; ks++) {
            uint32_t pah[4], pal[4];
            split_bf2(s[2 * ks][0],     s[2 * ks][1],     pah[0], pal[0]);
            split_bf2(s[2 * ks][2],     s[2 * ks][3],     pah[1], pal[1]);
            split_bf2(s[2 * ks + 1][0], s[2 * ks + 1][1], pah[2], pal[2]);
            split_bf2(s[2 * ks + 1][2], s[2 * ks + 1][3], pah[3], pal[3]);
            const int kp0 = ks * 8;
#pragma unroll
            for (int nt = 0; nt < 8; nt++) {
                int d = nt * 8 + gid;
                uint32_t bh0 = sVh[(kp0 + tg) * AVP + d];
                uint32_t bh1 = sVh[(kp0 + 4 + tg) * AVP + d];
                uint32_t bl0 = sVl[(kp0 + tg) * AVP + d];
                uint32_t bl1 = sVl[(kp0 + 4 + tg) * AVP + d];
                mma3(o[nt], pah, pal, bh0, bh1, bl0, bl1);
            }
        }
        __syncthreads();   // done reading this stage before it is reloaded
    }

    // ---- epilogue: normalize + split + write packed ----
    const int b = bh >> 4;
    const int hh = bh & 15;
#pragma unroll
    for (int h = 0; h < 2; h++) {
        float inv = 1.0f / l_[h];
        int n = qt * 128 + w * 16 + gid + h * 8;
        size_t rw = (size_t)(b * NSEQ + n) * 512;
#pragma unroll
        for (int nt = 0; nt < 8; nt++) {
            int cp = hh * 32 + nt * 4 + tg;
            uint32_t hw, lw;
            split_bf2(o[nt][2 * h] * inv, o[nt][2 * h + 1] * inv, hw, lw);
            g_ah[rw + cp] = hw;
            g_al[rw + cp] = lw;
        }
    }
}

// ---------------------------------------------------------------------------
// LayerNorm over last dim + residual.
// ---------------------------------------------------------------------------
__global__ __launch_bounds__(256) void ln_kernel(
    const float* __restrict__ query, const float* __restrict__ gamma,
    const float* __restrict__ beta, float* __restrict__ out)
{
    const int r = blockIdx.x;
    const float* x = g_proj + (size_t)r * DIMC;

    float v[4];
    float s = 0.f, ss = 0.f;
#pragma unroll
    for (int i = 0; i < 4; i++) {
        v[i] = x[threadIdx.x + 256 * i];
        s += v[i];
        ss += v[i] * v[i];
    }
#pragma unroll
    for (int ofs = 16; ofs > 0; ofs >>= 1) {
        s  += __shfl_xor_sync(0xffffffffu, s,  ofs);
        ss += __shfl_xor_sync(0xffffffffu, ss, ofs);
    }
    __shared__ float rs[8], rss[8];
    int w = threadIdx.x >> 5, lane = threadIdx.x & 31;
    if (lane == 0) { rs[w] = s; rss[w] = ss; }
    __syncthreads();
    if (threadIdx.x == 0) {
        float a = 0.f, b2 = 0.f;
#pragma unroll
        for (int i = 0; i < 8; i++) { a += rs[i]; b2 += rss[i]; }
        rs[0] = a; rss[0] = b2;
    }
    __syncthreads();
    const float mean = rs[0] * (1.0f / DIMC);
    const float var  = rss[0] * (1.0f / DIMC) - mean * mean;
    const float inv  = rsqrtf(var + 1e-5f);

#pragma unroll
    for (int i = 0; i < 4; i++) {
        int c = threadIdx.x + 256 * i;
        size_t idx = (size_t)r * DIMC + c;
        out[idx] = (v[i] - mean) * inv * gamma[c] + beta[c] + query[idx];
    }
}

// ---------------------------------------------------------------------------
extern "C" void kernel_launch(void* const* d_in, const int* in_sizes, int n_in,
                              void* d_out, int out_size)
{
    const float* query = (const float*)d_in[0];
    const float* key_  = (const float*)d_in[1];
    const float* value = (const float*)d_in[2];
    const float* Wq    = (const float*)d_in[3];
    const float* Wk    = (const float*)d_in[4];
    const float* Wv    = (const float*)d_in[5];
    const float* Wo    = (const float*)d_in[6];
    const float* bo    = (const float*)d_in[7];
    const float* gamma = (const float*)d_in[8];
    const float* beta  = (const float*)d_in[9];
    float* out = (float*)d_out;

    cudaFuncSetAttribute(attn_mma,
                         cudaFuncAttributeMaxDynamicSharedMemorySize, ATTN_SMEM);
    cudaFuncSetAttribute(mma_gemm_qkv,
                         cudaFuncAttributeMaxDynamicSharedMemorySize, GEMM_SMEM);
    cudaFuncSetAttribute(mma_gemm_wo,
                         cudaFuncAttributeMaxDynamicSharedMemorySize, GEMM_SMEM);

    // 0) split prep
    x_prep<<<dim3(MTOT * DIMC / 1024, 1, 3), 256>>>(query, key_, value);
    w_prep<<<dim3(WWRD / 1024, 1, 4), 256>>>(Wq, Wk, Wv, Wo);

    // 1) QKV projections
    mma_gemm_qkv<<<dim3(MTOT / 128, DIMC / 128, 3), 256, GEMM_SMEM>>>();
    // 1b) pack V pairs along seq
    v_pack<<<VPW / (256 * 4), 256>>>();
    // 2) Attention
    attn_mma<<<dim3(NSEQ / 128, BC * HEADS), 256, ATTN_SMEM>>>();
    // 3) Wo projection + bias
    mma_gemm_wo<<<dim3(MTOT / 128, DIMC / 128), 256, GEMM_SMEM>>>(bo);
    // 4) LayerNorm + residual
    ln_kernel<<<MTOT, 256>>>(query, gamma, beta, out);
}